// round 2
// baseline (speedup 1.0000x reference)
#include <cuda_runtime.h>
#include <math.h>

// ---------------- scratch (device globals: allocation-free contract) ----------------
__device__ float g_h1[256 * 256 * 400];          // conv1 out  [b][co][20][20]  104.9MB
__device__ float g_h2[256 * 9216];               // conv2 out  [b][co][6][6]     9.4MB
__device__ float g_u[256 * 9216];                // squashed   [b][flat]         9.4MB
__device__ float g_uhat[(size_t)256 * 1152 * 160]; // u_hat    [b][i][o][d]    188.7MB
__device__ float g_masked[256 * 160];
__device__ float g_d1[256 * 512];
__device__ float g_d2[256 * 1024];

// ---------------- conv1: [256,1,28,28] -> [256,256,20,20], 9x9 s1 ----------------
__global__ __launch_bounds__(128) void conv1_kernel(
    const float* __restrict__ x, const float* __restrict__ w,
    const float* __restrict__ bias) {
    __shared__ float xs[784];
    __shared__ float ws[128 * 81];
    int b = blockIdx.x;
    int cb = blockIdx.y * 128;
    int t = threadIdx.x;

    for (int idx = t; idx < 784; idx += 128) xs[idx] = x[b * 784 + idx];
    for (int idx = t; idx < 128 * 81; idx += 128) ws[idx] = w[cb * 81 + idx];
    __syncthreads();

    int co = cb + t;
    float bv = bias[co];
    float* outp = g_h1 + ((size_t)(b * 256 + co)) * 400;

    for (int oy = 0; oy < 20; oy++) {
        float acc[20];
#pragma unroll
        for (int j = 0; j < 20; j++) acc[j] = bv;
        for (int ky = 0; ky < 9; ky++) {
            float xr[28];
#pragma unroll
            for (int j = 0; j < 28; j++) xr[j] = xs[(oy + ky) * 28 + j];
#pragma unroll
            for (int kx = 0; kx < 9; kx++) {
                float wv = ws[t * 81 + ky * 9 + kx];
#pragma unroll
                for (int ox = 0; ox < 20; ox++) acc[ox] += wv * xr[ox + kx];
            }
        }
#pragma unroll
        for (int ox = 0; ox < 20; ox++) outp[oy * 20 + ox] = acc[ox];
    }
}

// ---------------- conv2 as implicit-im2col GEMM ----------------
// C[m=co, n=(b,oy,ox)] = sum_k A[m,k] * B[k,n],  M=256, N=9216, K=20736
// A = conv2_w [256,20736] (native OIHW layout). B gathered from g_h1.
__global__ __launch_bounds__(256) void conv2_gemm(
    const float* __restrict__ Wc, const float* __restrict__ bias) {
    __shared__ float As[16][128];
    __shared__ float Bs[16][128];
    __shared__ int nOff[128];
    __shared__ int oOff[128];

    int t = threadIdx.x;
    int bx = blockIdx.x, by = blockIdx.y;

    if (t < 128) {
        int n = bx * 128 + t;
        int b = n / 36;
        int pos = n - b * 36;
        int oy = pos / 6;
        int ox = pos - oy * 6;
        nOff[t] = b * 102400 + oy * 40 + ox * 2;   // b*256*400 + (2oy)*20 + 2ox
        oOff[t] = b * 9216 + pos;                  // output scatter base
    }
    __syncthreads();

    int arow = t >> 2;          // 0..63
    int ak = (t & 3) * 4;       // 0,4,8,12
    int bkr = t >> 4;           // 0..15
    int bng = (t & 15) * 8;     // 0..120
    int tx = t & 15, ty = t >> 4;

    float acc[8][8];
#pragma unroll
    for (int i = 0; i < 8; i++)
#pragma unroll
        for (int j = 0; j < 8; j++) acc[i][j] = 0.f;

    // prologue load of tile 0
    float4 a0 = *(const float4*)(Wc + (size_t)(by * 128 + arow) * 20736 + 0 + ak);
    float4 a1 = *(const float4*)(Wc + (size_t)(by * 128 + arow + 64) * 20736 + 0 + ak);
    float br[8];
    {
        int k = 0 + bkr;
        int ci = k / 81; int r = k - ci * 81;
        int ky = r / 9;  int kx = r - ky * 9;
        int ko = ci * 400 + ky * 20 + kx;
#pragma unroll
        for (int j = 0; j < 8; j++) br[j] = g_h1[ko + nOff[bng + j]];
    }

    for (int kk = 0; kk < 20736; kk += 16) {
        As[ak + 0][arow] = a0.x; As[ak + 1][arow] = a0.y;
        As[ak + 2][arow] = a0.z; As[ak + 3][arow] = a0.w;
        As[ak + 0][arow + 64] = a1.x; As[ak + 1][arow + 64] = a1.y;
        As[ak + 2][arow + 64] = a1.z; As[ak + 3][arow + 64] = a1.w;
#pragma unroll
        for (int j = 0; j < 8; j++) Bs[bkr][bng + j] = br[j];
        __syncthreads();

        bool more = (kk + 16) < 20736;
        if (more) {
            a0 = *(const float4*)(Wc + (size_t)(by * 128 + arow) * 20736 + (kk + 16) + ak);
            a1 = *(const float4*)(Wc + (size_t)(by * 128 + arow + 64) * 20736 + (kk + 16) + ak);
            int k = kk + 16 + bkr;
            int ci = k / 81; int r = k - ci * 81;
            int ky = r / 9;  int kx = r - ky * 9;
            int ko = ci * 400 + ky * 20 + kx;
#pragma unroll
            for (int j = 0; j < 8; j++) br[j] = g_h1[ko + nOff[bng + j]];
        }

#pragma unroll
        for (int kr = 0; kr < 16; kr++) {
            float af[8], bf[8];
            *(float4*)(af) = *(const float4*)&As[kr][ty * 8];
            *(float4*)(af + 4) = *(const float4*)&As[kr][ty * 8 + 4];
            *(float4*)(bf) = *(const float4*)&Bs[kr][tx * 8];
            *(float4*)(bf + 4) = *(const float4*)&Bs[kr][tx * 8 + 4];
#pragma unroll
            for (int mi = 0; mi < 8; mi++)
#pragma unroll
                for (int ni = 0; ni < 8; ni++) acc[mi][ni] += af[mi] * bf[ni];
        }
        __syncthreads();
    }

    // epilogue: scatter to g_h2 [b][co][pos]
#pragma unroll
    for (int mi = 0; mi < 8; mi++) {
        int m = by * 128 + ty * 8 + mi;
        float bv = bias[m];
#pragma unroll
        for (int ni = 0; ni < 8; ni++) {
            int n = tx * 8 + ni;
            g_h2[oOff[n] + m * 36] = acc[mi][ni] + bv;
        }
    }
}

// ---------------- squash over last spatial axis (groups of 6) ----------------
__global__ void squash_conv_kernel() {
    int rid = blockIdx.x * blockDim.x + threadIdx.x;  // 393216 rows of 6
    const float* p = g_h2 + (size_t)rid * 6;
    float v[6];
    float n2 = 0.f;
#pragma unroll
    for (int j = 0; j < 6; j++) { v[j] = p[j]; n2 += v[j] * v[j]; }
    float nrm = sqrtf(n2);
    float sc = (n2 / (1.f + n2)) / (nrm + 1e-7f);
    float* q = g_u + (size_t)rid * 6;
#pragma unroll
    for (int j = 0; j < 6; j++) q[j] = v[j] * sc;
}

// ---------------- u_hat: [b][i][o][d] = W[o][i][d][:] . u[b][i][:] ----------------
// one block per (o,i); thread = batch b. W load uniform -> L1 broadcast.
__global__ __launch_bounds__(256) void uhat_kernel(const float* __restrict__ Wc) {
    int oi = blockIdx.x;                  // 0..11519
    int o = oi / 1152;
    int i = oi - o * 1152;
    int b = threadIdx.x;

    const float* up = g_u + (size_t)b * 9216 + i * 8;
    float4 u0 = *(const float4*)(up);
    float4 u1 = *(const float4*)(up + 4);

    const float* wp = Wc + (size_t)(o * 1152 + i) * 128;
    float res[16];
#pragma unroll
    for (int d = 0; d < 16; d++) {
        float4 w0 = *(const float4*)(wp + d * 8);
        float4 w1 = *(const float4*)(wp + d * 8 + 4);
        res[d] = w0.x * u0.x + w0.y * u0.y + w0.z * u0.z + w0.w * u0.w
               + w1.x * u1.x + w1.y * u1.y + w1.z * u1.z + w1.w * u1.w;
    }
    float* op = g_uhat + (((size_t)b * 1152 + i) * 10 + o) * 16;
#pragma unroll
    for (int q = 0; q < 4; q++)
        *(float4*)(op + q * 4) =
            make_float4(res[q * 4], res[q * 4 + 1], res[q * 4 + 2], res[q * 4 + 3]);
}

// ---------------- dynamic routing (3 iters, fused into 3 passes) ----------------
// lane layout: lane = oh*16 + d (oh in {0,1}); og loop covers o = og*2+oh (5 ogs).
__device__ __forceinline__ void route_accum(
    const float uh[5], const float* v0s, const float* v1s,
    int p, int lane, float sacc[5]) {
    float c[5];
    float lg[5];
#pragma unroll
    for (int og = 0; og < 5; og++) {
        float tsum = uh[og] * v0s[og * 32 + lane];
        if (p == 2) tsum += uh[og] * v1s[og * 32 + lane];  // dot(v0+v1, uh)
        tsum += __shfl_xor_sync(0xffffffffu, tsum, 8);
        tsum += __shfl_xor_sync(0xffffffffu, tsum, 4);
        tsum += __shfl_xor_sync(0xffffffffu, tsum, 2);
        tsum += __shfl_xor_sync(0xffffffffu, tsum, 1);
        lg[og] = tsum;
    }
    float m = lg[0];
#pragma unroll
    for (int og = 1; og < 5; og++) m = fmaxf(m, lg[og]);
    m = fmaxf(m, __shfl_xor_sync(0xffffffffu, m, 16));
    float ssum = 0.f;
#pragma unroll
    for (int og = 0; og < 5; og++) { c[og] = expf(lg[og] - m); ssum += c[og]; }
    ssum += __shfl_xor_sync(0xffffffffu, ssum, 16);
    float inv = 1.f / ssum;
#pragma unroll
    for (int og = 0; og < 5; og++) sacc[og] += (c[og] * inv) * uh[og];
}

__global__ __launch_bounds__(256) void routing_kernel(float* __restrict__ out_len) {
    int b = blockIdx.x;
    int tid = threadIdx.x;
    int lane = tid & 31, warp = tid >> 5;

    __shared__ float v0s[160], v1s[160], v2s[160];
    __shared__ float spart[8 * 160];
    __shared__ float sred[160];
    __shared__ float scale_s[10], len_s[10];
    __shared__ int amax_s;

    const float* base = g_uhat + (size_t)b * 184320;

    for (int p = 0; p < 3; p++) {
        float sacc[5] = {0.f, 0.f, 0.f, 0.f, 0.f};
        for (int ii = warp; ii < 1152; ii += 16) {
            const float* pA = base + ii * 160;
            const float* pB = base + (ii + 8) * 160;
            float uhA[5], uhB[5];
#pragma unroll
            for (int og = 0; og < 5; og++) uhA[og] = pA[og * 32 + lane];
#pragma unroll
            for (int og = 0; og < 5; og++) uhB[og] = pB[og * 32 + lane];
            if (p == 0) {
#pragma unroll
                for (int og = 0; og < 5; og++) sacc[og] += 0.1f * (uhA[og] + uhB[og]);
            } else {
                route_accum(uhA, v0s, v1s, p, lane, sacc);
                route_accum(uhB, v0s, v1s, p, lane, sacc);
            }
        }
#pragma unroll
        for (int og = 0; og < 5; og++) spart[warp * 160 + og * 32 + lane] = sacc[og];
        __syncthreads();
        if (tid < 160) {
            float tot = 0.f;
#pragma unroll
            for (int w = 0; w < 8; w++) tot += spart[w * 160 + tid];
            sred[tid] = tot;
        }
        __syncthreads();
        if (tid < 10) {
            float n2 = 0.f;
#pragma unroll
            for (int d = 0; d < 16; d++) { float xv = sred[tid * 16 + d]; n2 += xv * xv; }
            float nrm = sqrtf(n2);
            scale_s[tid] = (n2 / (1.f + n2)) / (nrm + 1e-7f);
            if (p == 2) len_s[tid] = (n2 / (1.f + n2)) * (nrm / (nrm + 1e-7f));
        }
        __syncthreads();
        float* vdst = (p == 0) ? v0s : ((p == 1) ? v1s : v2s);
        if (tid < 160) vdst[tid] = sred[tid] * scale_s[tid >> 4];
        __syncthreads();
    }

    if (tid == 0) {
        int bi = 0;
        float best = len_s[0];
#pragma unroll
        for (int o = 1; o < 10; o++)
            if (len_s[o] > best) { best = len_s[o]; bi = o; }
        amax_s = bi;
    }
    if (tid < 10) out_len[b * 10 + tid] = len_s[tid];
    __syncthreads();
    if (tid < 160) g_masked[b * 160 + tid] = ((tid >> 4) == amax_s) ? v2s[tid] : 0.f;
}

// ---------------- decoder GEMM (64x64x16 tile, 4x4 micro), epilogue fused ----------------
// EPI: 1 = relu, 2 = sigmoid
template <int EPI>
__global__ __launch_bounds__(256) void gemm_epi(
    const float* __restrict__ A, const float* __restrict__ W,
    const float* __restrict__ bias, float* __restrict__ C,
    int M, int N, int K) {
    __shared__ float As[16][64];
    __shared__ float Bs[16][64];
    int t = threadIdx.x;
    int bx = blockIdx.x, by = blockIdx.y;
    int arow = t >> 2, ak = (t & 3) * 4;
    int bkr = t >> 4, bnc = (t & 15) * 4;
    int tx = t & 15, ty = t >> 4;

    float acc[4][4];
#pragma unroll
    for (int i = 0; i < 4; i++)
#pragma unroll
        for (int j = 0; j < 4; j++) acc[i][j] = 0.f;

    for (int kk = 0; kk < K; kk += 16) {
        float4 av = *(const float4*)(A + (size_t)(by * 64 + arow) * K + kk + ak);
        int n0 = bx * 64 + bnc;
        float4 bv = make_float4(0.f, 0.f, 0.f, 0.f);
        if (n0 < N) bv = *(const float4*)(W + (size_t)(kk + bkr) * N + n0);
        As[ak + 0][arow] = av.x; As[ak + 1][arow] = av.y;
        As[ak + 2][arow] = av.z; As[ak + 3][arow] = av.w;
        *(float4*)&Bs[bkr][bnc] = bv;
        __syncthreads();
#pragma unroll
        for (int kr = 0; kr < 16; kr++) {
            float af[4], bf[4];
            *(float4*)af = *(const float4*)&As[kr][ty * 4];
            *(float4*)bf = *(const float4*)&Bs[kr][tx * 4];
#pragma unroll
            for (int mi = 0; mi < 4; mi++)
#pragma unroll
                for (int ni = 0; ni < 4; ni++) acc[mi][ni] += af[mi] * bf[ni];
        }
        __syncthreads();
    }

#pragma unroll
    for (int mi = 0; mi < 4; mi++) {
        int m = by * 64 + ty * 4 + mi;
#pragma unroll
        for (int ni = 0; ni < 4; ni++) {
            int n = bx * 64 + tx * 4 + ni;
            if (n < N) {
                float v = acc[mi][ni] + bias[n];
                if (EPI == 1) v = fmaxf(v, 0.f);
                if (EPI == 2) v = 1.f / (1.f + expf(-v));
                C[(size_t)m * N + n] = v;
            }
        }
    }
}

// ---------------- launch ----------------
extern "C" void kernel_launch(void* const* d_in, const int* in_sizes, int n_in,
                              void* d_out, int out_size) {
    const float* x     = (const float*)d_in[0];
    const float* c1w   = (const float*)d_in[1];
    const float* c1b   = (const float*)d_in[2];
    const float* c2w   = (const float*)d_in[3];
    const float* c2b   = (const float*)d_in[4];
    const float* Wcaps = (const float*)d_in[5];
    const float* dw1   = (const float*)d_in[6];
    const float* db1   = (const float*)d_in[7];
    const float* dw2   = (const float*)d_in[8];
    const float* db2   = (const float*)d_in[9];
    const float* dw3   = (const float*)d_in[10];
    const float* db3   = (const float*)d_in[11];
    float* out = (float*)d_out;

    float* g_d1_ptr; cudaGetSymbolAddress((void**)&g_d1_ptr, g_d1);
    float* g_d2_ptr; cudaGetSymbolAddress((void**)&g_d2_ptr, g_d2);
    float* g_m_ptr;  cudaGetSymbolAddress((void**)&g_m_ptr, g_masked);

    conv1_kernel<<<dim3(256, 2), 128>>>(x, c1w, c1b);
    conv2_gemm<<<dim3(72, 2), 256>>>(c2w, c2b);
    squash_conv_kernel<<<1536, 256>>>();
    uhat_kernel<<<11520, 256>>>(Wcaps);
    routing_kernel<<<256, 256>>>(out);                       // lengths -> out[0..2560)
    gemm_epi<1><<<dim3(8, 4), 256>>>(g_m_ptr, dw1, db1, g_d1_ptr, 256, 512, 160);
    gemm_epi<1><<<dim3(16, 4), 256>>>(g_d1_ptr, dw2, db2, g_d2_ptr, 256, 1024, 512);
    gemm_epi<2><<<dim3(13, 4), 256>>>(g_d2_ptr, dw3, db3, out + 2560, 256, 784, 1024);
}

// round 4
// speedup vs baseline: 1.8852x; 1.8852x over previous
#include <cuda_runtime.h>
#include <math.h>
#include <stdint.h>

// ---------------- scratch (device globals: allocation-free contract) ----------------
__device__ float g_h1[256 * 256 * 400];            // conv1 out [b][co][20][20]
__device__ float g_h2[256 * 9216];                 // conv2 out [b][pos][co]  (transposed)
__device__ float g_u[256 * 9216];                  // squashed  [b][co*36+pos]
__device__ float g_uhat[(size_t)256 * 1152 * 160]; // u_hat     [b][i][o][d]
__device__ float g_masked[256 * 160];
__device__ float g_d1[256 * 512];
__device__ float g_d2[256 * 1024];

__device__ __forceinline__ uint32_t f2tf(float x) {
    uint32_t o;
    asm("cvt.rna.tf32.f32 %0, %1;" : "=r"(o) : "f"(x));
    return o;
}

__device__ __forceinline__ void mma_tf32(float* c, const uint32_t* a, const uint32_t* b) {
    asm volatile(
        "mma.sync.aligned.m16n8k8.row.col.f32.tf32.tf32.f32 "
        "{%0,%1,%2,%3}, {%4,%5,%6,%7}, {%8,%9}, {%0,%1,%2,%3};"
        : "+f"(c[0]), "+f"(c[1]), "+f"(c[2]), "+f"(c[3])
        : "r"(a[0]), "r"(a[1]), "r"(a[2]), "r"(a[3]), "r"(b[0]), "r"(b[1]));
}

// ---------------- conv1: [256,1,28,28] -> [256,256,20,20], 9x9 s1 ----------------
__global__ __launch_bounds__(128) void conv1_kernel(
    const float* __restrict__ x, const float* __restrict__ w,
    const float* __restrict__ bias) {
    __shared__ float xs[784];
    __shared__ float ws[128 * 81];
    int b = blockIdx.x;
    int cb = blockIdx.y * 128;
    int t = threadIdx.x;

    for (int idx = t; idx < 784; idx += 128) xs[idx] = x[b * 784 + idx];
    for (int idx = t; idx < 128 * 81; idx += 128) ws[idx] = w[cb * 81 + idx];
    __syncthreads();

    int co = cb + t;
    float bv = bias[co];
    float* outp = g_h1 + ((size_t)(b * 256 + co)) * 400;

    for (int oy = 0; oy < 20; oy++) {
        float acc[20];
#pragma unroll
        for (int j = 0; j < 20; j++) acc[j] = bv;
        for (int ky = 0; ky < 9; ky++) {
            float xr[28];
#pragma unroll
            for (int j = 0; j < 28; j++) xr[j] = xs[(oy + ky) * 28 + j];
#pragma unroll
            for (int kx = 0; kx < 9; kx++) {
                float wv = ws[t * 81 + ky * 9 + kx];
#pragma unroll
                for (int ox = 0; ox < 20; ox++) acc[ox] += wv * xr[ox + kx];
            }
        }
#pragma unroll
        for (int ox = 0; ox < 20; ox++) outp[oy * 20 + ox] = acc[ox];
    }
}

// ---------------- conv2 as tf32 mma.sync implicit-im2col GEMM ----------------
// D[m=co(128), n=(b,pos)(128)]; K = 20736 in tiles of 32. 8 warps, warp tile 64x32.
#define LDA 36
#define LDB 136

__global__ __launch_bounds__(256) void conv2_mma(
    const float* __restrict__ Wc, const float* __restrict__ bias) {
    __shared__ uint32_t As2[128][LDA];   // [m][k], tf32 bits
    __shared__ uint32_t Bs[32][LDB];     // [k][n], tf32 bits
    __shared__ int nOff[128];
    __shared__ int o2Off[128];

    int t = threadIdx.x;
    int bx = blockIdx.x, by = blockIdx.y;
    int wid = t >> 5, lane = t & 31;
    int g = lane >> 2, tg = lane & 3;
    int warp_m = wid >> 2, warp_n = wid & 3;

    if (t < 128) {
        int n = bx * 128 + t;
        int b = n / 36, pos = n - b * 36;
        int oy = pos / 6, ox = pos - oy * 6;
        nOff[t] = b * 102400 + oy * 40 + ox * 2;   // into g_h1 (b*256*400 + 2oy*20 + 2ox)
        o2Off[t] = (b * 36 + pos) * 256;           // into g_h2 (transposed)
    }
    __syncthreads();

    // loader roles
    int arow = t >> 1, ahalf = (t & 1) * 16;   // A: 128 rows x 32 k, 16 floats/thread
    int bkr = t >> 3, bng = (t & 7) * 16;      // B: 32 k-rows x 128 n, 16 gathers/thread

    const float* abase = Wc + (size_t)(by * 128 + arow) * 20736 + ahalf;

    float4 aR[4];
    float bR[16];

    // prologue: fetch tile 0 into regs
#pragma unroll
    for (int q = 0; q < 4; q++) aR[q] = *(const float4*)(abase + q * 4);
    {
        int k = bkr;
        int ci = k / 81; int rr = k - ci * 81;
        int ky = rr / 9;  int kx = rr - ky * 9;
        int ko = ci * 400 + ky * 20 + kx;
#pragma unroll
        for (int j = 0; j < 16; j++) bR[j] = g_h1[ko + nOff[bng + j]];
    }

    float acc[4][4][4];
#pragma unroll
    for (int mi = 0; mi < 4; mi++)
#pragma unroll
        for (int ni = 0; ni < 4; ni++)
#pragma unroll
            for (int r = 0; r < 4; r++) acc[mi][ni][r] = 0.f;

    for (int kk = 0; kk < 20736; kk += 32) {
        // stage regs -> smem (tf32-rounded)
#pragma unroll
        for (int q = 0; q < 4; q++) {
            uint4 u;
            u.x = f2tf(aR[q].x); u.y = f2tf(aR[q].y);
            u.z = f2tf(aR[q].z); u.w = f2tf(aR[q].w);
            *(uint4*)&As2[arow][ahalf + q * 4] = u;
        }
#pragma unroll
        for (int q = 0; q < 4; q++) {
            uint4 u;
            u.x = f2tf(bR[q * 4 + 0]); u.y = f2tf(bR[q * 4 + 1]);
            u.z = f2tf(bR[q * 4 + 2]); u.w = f2tf(bR[q * 4 + 3]);
            *(uint4*)&Bs[bkr][bng + q * 4] = u;
        }
        __syncthreads();

        // prefetch next tile
        if (kk + 32 < 20736) {
            const float* ap = abase + kk + 32;
#pragma unroll
            for (int q = 0; q < 4; q++) aR[q] = *(const float4*)(ap + q * 4);
            int k = kk + 32 + bkr;
            int ci = k / 81; int rr = k - ci * 81;
            int ky = rr / 9;  int kx = rr - ky * 9;
            int ko = ci * 400 + ky * 20 + kx;
#pragma unroll
            for (int j = 0; j < 16; j++) bR[j] = g_h1[ko + nOff[bng + j]];
        }

        // compute: 4 k-steps of m16n8k8
#pragma unroll
        for (int ks = 0; ks < 4; ks++) {
            int k0 = ks * 8 + tg;
            uint32_t a_f[4][4];
            uint32_t b_f[4][2];
#pragma unroll
            for (int mi = 0; mi < 4; mi++) {
                int m0 = warp_m * 64 + mi * 16 + g;
                a_f[mi][0] = As2[m0][k0];
                a_f[mi][1] = As2[m0 + 8][k0];
                a_f[mi][2] = As2[m0][k0 + 4];
                a_f[mi][3] = As2[m0 + 8][k0 + 4];
            }
#pragma unroll
            for (int ni = 0; ni < 4; ni++) {
                int n0 = warp_n * 32 + ni * 8 + g;
                b_f[ni][0] = Bs[k0][n0];
                b_f[ni][1] = Bs[k0 + 4][n0];
            }
#pragma unroll
            for (int mi = 0; mi < 4; mi++)
#pragma unroll
                for (int ni = 0; ni < 4; ni++)
                    mma_tf32(acc[mi][ni], a_f[mi], b_f[ni]);
        }
        __syncthreads();
    }

    // epilogue: scatter to g_h2 [b][pos][co] with bias
#pragma unroll
    for (int mi = 0; mi < 4; mi++) {
        int m0 = warp_m * 64 + mi * 16 + g;
        int mg0 = by * 128 + m0;
        float bv0 = bias[mg0];
        float bv1 = bias[mg0 + 8];
#pragma unroll
        for (int ni = 0; ni < 4; ni++) {
            int n0 = warp_n * 32 + ni * 8 + 2 * tg;
            int o0 = o2Off[n0], o1 = o2Off[n0 + 1];
            g_h2[o0 + mg0]     = acc[mi][ni][0] + bv0;
            g_h2[o1 + mg0]     = acc[mi][ni][1] + bv0;
            g_h2[o0 + mg0 + 8] = acc[mi][ni][2] + bv1;
            g_h2[o1 + mg0 + 8] = acc[mi][ni][3] + bv1;
        }
    }
}

// ---------------- squash over last spatial axis (groups of 6 along ox) ----------------
// reads g_h2 [b][pos][co], writes g_u [b][co*36+pos]
__global__ void squash_conv_kernel() {
    int gid = blockIdx.x * blockDim.x + threadIdx.x;  // 393216 = 256*6*256
    int b = gid / 1536;
    int rem = gid - b * 1536;
    int oy = rem >> 8;
    int co = rem & 255;
    float v[6];
    float n2 = 0.f;
#pragma unroll
    for (int j = 0; j < 6; j++) {
        v[j] = g_h2[(size_t)(b * 36 + oy * 6 + j) * 256 + co];
        n2 += v[j] * v[j];
    }
    float nrm = sqrtf(n2);
    float sc = (n2 / (1.f + n2)) / (nrm + 1e-7f);
    float* q = g_u + (size_t)b * 9216 + co * 36 + oy * 6;
#pragma unroll
    for (int j = 0; j < 6; j++) q[j] = v[j] * sc;
}

// ---------------- u_hat: coalesced writes. block = input capsule i ----------------
__global__ __launch_bounds__(320) void uhat_kernel2(const float* __restrict__ Wc) {
    __shared__ float u_s[2048];
    int i = blockIdx.x;
    int t = threadIdx.x;
    int b2 = t / 40;        // 0..7
    int od4 = t - b2 * 40;  // 0..39

    for (int idx = t; idx < 2048; idx += 320) {
        int b = idx >> 3, e = idx & 7;
        u_s[idx] = g_u[(size_t)b * 9216 + i * 8 + e];
    }
    int od0 = od4 * 4;
    int o = od0 >> 4;
    int d0 = od0 & 15;
    const float* wp = Wc + ((size_t)(o * 1152 + i) * 16 + d0) * 8;
    float w[4][8];
#pragma unroll
    for (int q = 0; q < 4; q++) {
        float4 w0 = *(const float4*)(wp + q * 8);
        float4 w1 = *(const float4*)(wp + q * 8 + 4);
        w[q][0] = w0.x; w[q][1] = w0.y; w[q][2] = w0.z; w[q][3] = w0.w;
        w[q][4] = w1.x; w[q][5] = w1.y; w[q][6] = w1.z; w[q][7] = w1.w;
    }
    __syncthreads();
    for (int bo = 0; bo < 32; bo++) {
        int b = bo * 8 + b2;
        float ue[8];
#pragma unroll
        for (int e = 0; e < 8; e++) ue[e] = u_s[b * 8 + e];
        float acc[4];
#pragma unroll
        for (int q = 0; q < 4; q++) {
            float a = 0.f;
#pragma unroll
            for (int e = 0; e < 8; e++) a += w[q][e] * ue[e];
            acc[q] = a;
        }
        *(float4*)(g_uhat + ((size_t)b * 1152 + i) * 160 + od0) =
            make_float4(acc[0], acc[1], acc[2], acc[3]);
    }
}

// ---------------- dynamic routing (3 iters fused) ----------------
__device__ __forceinline__ void route_accum(
    const float uh[5], const float* v0s, const float* v1s,
    int p, int lane, float sacc[5]) {
    float c[5];
    float lg[5];
#pragma unroll
    for (int og = 0; og < 5; og++) {
        float tsum = uh[og] * v0s[og * 32 + lane];
        if (p == 2) tsum += uh[og] * v1s[og * 32 + lane];
        tsum += __shfl_xor_sync(0xffffffffu, tsum, 8);
        tsum += __shfl_xor_sync(0xffffffffu, tsum, 4);
        tsum += __shfl_xor_sync(0xffffffffu, tsum, 2);
        tsum += __shfl_xor_sync(0xffffffffu, tsum, 1);
        lg[og] = tsum;
    }
    float m = lg[0];
#pragma unroll
    for (int og = 1; og < 5; og++) m = fmaxf(m, lg[og]);
    m = fmaxf(m, __shfl_xor_sync(0xffffffffu, m, 16));
    float ssum = 0.f;
#pragma unroll
    for (int og = 0; og < 5; og++) { c[og] = expf(lg[og] - m); ssum += c[og]; }
    ssum += __shfl_xor_sync(0xffffffffu, ssum, 16);
    float inv = 1.f / ssum;
#pragma unroll
    for (int og = 0; og < 5; og++) sacc[og] += (c[og] * inv) * uh[og];
}

__global__ __launch_bounds__(256) void routing_kernel(float* __restrict__ out_len) {
    int b = blockIdx.x;
    int tid = threadIdx.x;
    int lane = tid & 31, warp = tid >> 5;

    __shared__ float v0s[160], v1s[160], v2s[160];
    __shared__ float spart[8 * 160];
    __shared__ float sred[160];
    __shared__ float scale_s[10], len_s[10];
    __shared__ int amax_s;

    const float* base = g_uhat + (size_t)b * 184320;

    for (int p = 0; p < 3; p++) {
        float sacc[5] = {0.f, 0.f, 0.f, 0.f, 0.f};
        for (int ii = warp; ii < 1152; ii += 16) {
            const float* pA = base + ii * 160;
            const float* pB = base + (ii + 8) * 160;
            float uhA[5], uhB[5];
#pragma unroll
            for (int og = 0; og < 5; og++) uhA[og] = pA[og * 32 + lane];
#pragma unroll
            for (int og = 0; og < 5; og++) uhB[og] = pB[og * 32 + lane];
            if (p == 0) {
#pragma unroll
                for (int og = 0; og < 5; og++) sacc[og] += 0.1f * (uhA[og] + uhB[og]);
            } else {
                route_accum(uhA, v0s, v1s, p, lane, sacc);
                route_accum(uhB, v0s, v1s, p, lane, sacc);
            }
        }
#pragma unroll
        for (int og = 0; og < 5; og++) spart[warp * 160 + og * 32 + lane] = sacc[og];
        __syncthreads();
        if (tid < 160) {
            float tot = 0.f;
#pragma unroll
            for (int w = 0; w < 8; w++) tot += spart[w * 160 + tid];
            sred[tid] = tot;
        }
        __syncthreads();
        if (tid < 10) {
            float n2 = 0.f;
#pragma unroll
            for (int d = 0; d < 16; d++) { float xv = sred[tid * 16 + d]; n2 += xv * xv; }
            float nrm = sqrtf(n2);
            scale_s[tid] = (n2 / (1.f + n2)) / (nrm + 1e-7f);
            if (p == 2) len_s[tid] = (n2 / (1.f + n2)) * (nrm / (nrm + 1e-7f));
        }
        __syncthreads();
        float* vdst = (p == 0) ? v0s : ((p == 1) ? v1s : v2s);
        if (tid < 160) vdst[tid] = sred[tid] * scale_s[tid >> 4];
        __syncthreads();
    }

    if (tid == 0) {
        int bi = 0;
        float best = len_s[0];
#pragma unroll
        for (int o = 1; o < 10; o++)
            if (len_s[o] > best) { best = len_s[o]; bi = o; }
        amax_s = bi;
    }
    if (tid < 10) out_len[b * 10 + tid] = len_s[tid];
    __syncthreads();
    if (tid < 160) g_masked[b * 160 + tid] = ((tid >> 4) == amax_s) ? v2s[tid] : 0.f;
}

// ---------------- decoder GEMM (64x64x16 tile, 4x4 micro), epilogue fused ----------------
template <int EPI>
__global__ __launch_bounds__(256) void gemm_epi(
    const float* __restrict__ A, const float* __restrict__ W,
    const float* __restrict__ bias, float* __restrict__ C,
    int M, int N, int K) {
    __shared__ float As[16][64];
    __shared__ float Bs[16][64];
    int t = threadIdx.x;
    int bx = blockIdx.x, by = blockIdx.y;
    int arow = t >> 2, ak = (t & 3) * 4;
    int bkr = t >> 4, bnc = (t & 15) * 4;
    int tx = t & 15, ty = t >> 4;

    float acc[4][4];
#pragma unroll
    for (int i = 0; i < 4; i++)
#pragma unroll
        for (int j = 0; j < 4; j++) acc[i][j] = 0.f;

    for (int kk = 0; kk < K; kk += 16) {
        float4 av = *(const float4*)(A + (size_t)(by * 64 + arow) * K + kk + ak);
        int n0 = bx * 64 + bnc;
        float4 bv = make_float4(0.f, 0.f, 0.f, 0.f);
        if (n0 < N) bv = *(const float4*)(W + (size_t)(kk + bkr) * N + n0);
        As[ak + 0][arow] = av.x; As[ak + 1][arow] = av.y;
        As[ak + 2][arow] = av.z; As[ak + 3][arow] = av.w;
        *(float4*)&Bs[bkr][bnc] = bv;
        __syncthreads();
#pragma unroll
        for (int kr = 0; kr < 16; kr++) {
            float af[4], bf[4];
            *(float4*)af = *(const float4*)&As[kr][ty * 4];
            *(float4*)bf = *(const float4*)&Bs[kr][tx * 4];
#pragma unroll
            for (int mi = 0; mi < 4; mi++)
#pragma unroll
                for (int ni = 0; ni < 4; ni++) acc[mi][ni] += af[mi] * bf[ni];
        }
        __syncthreads();
    }

#pragma unroll
    for (int mi = 0; mi < 4; mi++) {
        int m = by * 64 + ty * 4 + mi;
#pragma unroll
        for (int ni = 0; ni < 4; ni++) {
            int n = bx * 64 + tx * 4 + ni;
            if (n < N) {
                float v = acc[mi][ni] + bias[n];
                if (EPI == 1) v = fmaxf(v, 0.f);
                if (EPI == 2) v = 1.f / (1.f + expf(-v));
                C[(size_t)m * N + n] = v;
            }
        }
    }
}

// ---------------- launch ----------------
extern "C" void kernel_launch(void* const* d_in, const int* in_sizes, int n_in,
                              void* d_out, int out_size) {
    const float* x     = (const float*)d_in[0];
    const float* c1w   = (const float*)d_in[1];
    const float* c1b   = (const float*)d_in[2];
    const float* c2w   = (const float*)d_in[3];
    const float* c2b   = (const float*)d_in[4];
    const float* Wcaps = (const float*)d_in[5];
    const float* dw1   = (const float*)d_in[6];
    const float* db1   = (const float*)d_in[7];
    const float* dw2   = (const float*)d_in[8];
    const float* db2   = (const float*)d_in[9];
    const float* dw3   = (const float*)d_in[10];
    const float* db3   = (const float*)d_in[11];
    float* out = (float*)d_out;

    float* g_d1_ptr; cudaGetSymbolAddress((void**)&g_d1_ptr, g_d1);
    float* g_d2_ptr; cudaGetSymbolAddress((void**)&g_d2_ptr, g_d2);
    float* g_m_ptr;  cudaGetSymbolAddress((void**)&g_m_ptr, g_masked);

    conv1_kernel<<<dim3(256, 2), 128>>>(x, c1w, c1b);
    conv2_mma<<<dim3(72, 2), 256>>>(c2w, c2b);
    squash_conv_kernel<<<1536, 256>>>();
    uhat_kernel2<<<1152, 320>>>(Wcaps);
    routing_kernel<<<256, 256>>>(out);
    gemm_epi<1><<<dim3(8, 4), 256>>>(g_m_ptr, dw1, db1, g_d1_ptr, 256, 512, 160);
    gemm_epi<1><<<dim3(16, 4), 256>>>(g_d1_ptr, dw2, db2, g_d2_ptr, 256, 1024, 512);
    gemm_epi<2><<<dim3(13, 4), 256>>>(g_d2_ptr, dw3, db3, out + 2560, 256, 784, 1024);
}

// round 5
// speedup vs baseline: 2.2682x; 1.2032x over previous
#include <cuda_runtime.h>
#include <cuda_fp16.h>
#include <math.h>
#include <stdint.h>

// ---------------- scratch (device globals: allocation-free contract) ----------------
__device__ float g_h1[256 * 400 * 256];             // conv1 out [b][y][x][ci]  (channel-last)
__device__ float g_wt[256 * 20736];                 // conv2 W   [co][ky*9+kx][ci]
__device__ float g_h2[256 * 9216];                  // conv2 out [b][pos][co]
__device__ float g_u[256 * 9216];                   // squashed  [b][co*36+pos]
__device__ __half g_uhat[(size_t)256 * 1152 * 160]; // u_hat     [b][i][o][d] fp16
__device__ float g_masked[256 * 160];
__device__ float g_d1[256 * 512];
__device__ float g_d2[256 * 1024];

__device__ __forceinline__ uint32_t f2tf(float x) {
    uint32_t o;
    asm("cvt.rna.tf32.f32 %0, %1;" : "=r"(o) : "f"(x));
    return o;
}
__device__ __forceinline__ void mma_tf32(float* c, const uint32_t* a, const uint32_t* b) {
    asm volatile(
        "mma.sync.aligned.m16n8k8.row.col.f32.tf32.tf32.f32 "
        "{%0,%1,%2,%3}, {%4,%5,%6,%7}, {%8,%9}, {%0,%1,%2,%3};"
        : "+f"(c[0]), "+f"(c[1]), "+f"(c[2]), "+f"(c[3])
        : "r"(a[0]), "r"(a[1]), "r"(a[2]), "r"(a[3]), "r"(b[0]), "r"(b[1]));
}

// ---------------- conv1: [256,1,28,28] -> [b][y][x][co] channel-last ----------------
__global__ __launch_bounds__(128) void conv1_kernel(
    const float* __restrict__ x, const float* __restrict__ w,
    const float* __restrict__ bias) {
    __shared__ float xs[784];
    __shared__ float ws[128 * 81];
    int b = blockIdx.x;
    int cb = blockIdx.y * 128;
    int t = threadIdx.x;

    for (int idx = t; idx < 784; idx += 128) xs[idx] = x[b * 784 + idx];
    for (int idx = t; idx < 128 * 81; idx += 128) ws[idx] = w[cb * 81 + idx];
    __syncthreads();

    int co = cb + t;
    float bv = bias[co];
    float* outp = g_h1 + (size_t)b * 400 * 256 + co;

    for (int oy = 0; oy < 20; oy++) {
        float acc[20];
#pragma unroll
        for (int j = 0; j < 20; j++) acc[j] = bv;
        for (int ky = 0; ky < 9; ky++) {
            float xr[28];
#pragma unroll
            for (int j = 0; j < 28; j++) xr[j] = xs[(oy + ky) * 28 + j];
#pragma unroll
            for (int kx = 0; kx < 9; kx++) {
                float wv = ws[t * 81 + ky * 9 + kx];
#pragma unroll
                for (int ox = 0; ox < 20; ox++) acc[ox] += wv * xr[ox + kx];
            }
        }
#pragma unroll
        for (int ox = 0; ox < 20; ox++) outp[(oy * 20 + ox) * 256] = acc[ox];
    }
}

// ---------------- conv2 weight transpose: [co][ci][ky][kx] -> [co][ky*9+kx][ci] ----------------
__global__ void wtrans_kernel(const float* __restrict__ Wc) {
    extern __shared__ float s[];  // 20736 floats
    int co = blockIdx.x;
    int t = threadIdx.x;
    const float* src = Wc + (size_t)co * 20736;
    for (int idx = t; idx < 20736; idx += 256) s[idx] = src[idx];
    __syncthreads();
    float* dst = g_wt + (size_t)co * 20736;
    for (int idx = t; idx < 20736; idx += 256) {
        int j = idx >> 8, ci = idx & 255;          // k = j*256 + ci
        dst[idx] = s[ci * 81 + j];                 // stride 81 mod 32 = 17: conflict-free
    }
}

// ---------------- conv2 as tf32 mma.sync implicit-im2col GEMM ----------------
// D[m=co(128), n=(b,pos)(128)]; K = 81*256 ordered (ky,kx,ci); k-tile = 32 contiguous ci.
#define LDA 36
#define LDB 136

__global__ __launch_bounds__(256) void conv2_mma(const float* __restrict__ bias) {
    __shared__ uint32_t As2[128][LDA];   // [m][k] tf32 bits
    __shared__ uint32_t Bs[32][LDB];     // [k][n] tf32 bits
    __shared__ int nOffT[128];
    __shared__ int o2Off[128];

    int t = threadIdx.x;
    int bx = blockIdx.x, by = blockIdx.y;
    int wid = t >> 5, lane = t & 31;
    int g = lane >> 2, tg = lane & 3;
    int warp_m = wid >> 2, warp_n = wid & 3;

    if (t < 128) {
        int n = bx * 128 + t;
        int b = n / 36, pos = n - b * 36;
        int oy = pos / 6, ox = pos - oy * 6;
        nOffT[t] = (b * 400 + oy * 40 + ox * 2) * 256;   // into g_h1 channel-last
        o2Off[t] = (b * 36 + pos) * 256;                 // into g_h2 [b][pos][co]
    }
    __syncthreads();

    // loader roles (all contiguous float4 loads)
    int arow = t >> 1, ahalf = (t & 1) * 16;   // A: 128 rows x 32 k
    int bn = t >> 1, bch = (t & 1) * 16;       // B: 128 n x 32 ci

    const float* abase = g_wt + (size_t)(by * 128 + arow) * 20736;

    float4 aR[4], bRv[4];
    int bOffBase = nOffT[bn];

    // tile i: kxy = i>>3 (ky*9+kx), cib = (i&7)*32
    {
        const float* ap = abase + ahalf;  // i=0: kxy=0, cib=0
        const float* bp = g_h1 + bOffBase + bch;
#pragma unroll
        for (int q = 0; q < 4; q++) aR[q] = *(const float4*)(ap + q * 4);
#pragma unroll
        for (int q = 0; q < 4; q++) bRv[q] = *(const float4*)(bp + q * 4);
    }

    float acc[4][4][4];
#pragma unroll
    for (int mi = 0; mi < 4; mi++)
#pragma unroll
        for (int ni = 0; ni < 4; ni++)
#pragma unroll
            for (int r = 0; r < 4; r++) acc[mi][ni][r] = 0.f;

    const int ITERS = 648;  // 81 * 8
    for (int i = 0; i < ITERS; i++) {
        // stage regs -> smem (tf32-rounded)
#pragma unroll
        for (int q = 0; q < 4; q++) {
            uint4 u;
            u.x = f2tf(aR[q].x); u.y = f2tf(aR[q].y);
            u.z = f2tf(aR[q].z); u.w = f2tf(aR[q].w);
            *(uint4*)&As2[arow][ahalf + q * 4] = u;
        }
#pragma unroll
        for (int q = 0; q < 4; q++) {
            Bs[bch + q * 4 + 0][bn] = f2tf(bRv[q].x);
            Bs[bch + q * 4 + 1][bn] = f2tf(bRv[q].y);
            Bs[bch + q * 4 + 2][bn] = f2tf(bRv[q].z);
            Bs[bch + q * 4 + 3][bn] = f2tf(bRv[q].w);
        }
        __syncthreads();

        // prefetch next tile
        if (i + 1 < ITERS) {
            int ii = i + 1;
            int kxy = ii >> 3, cib = (ii & 7) << 5;
            int ky = kxy / 9, kx = kxy - ky * 9;
            const float* ap = abase + kxy * 256 + cib + ahalf;
            const float* bp = g_h1 + bOffBase + (ky * 20 + kx) * 256 + cib + bch;
#pragma unroll
            for (int q = 0; q < 4; q++) aR[q] = *(const float4*)(ap + q * 4);
#pragma unroll
            for (int q = 0; q < 4; q++) bRv[q] = *(const float4*)(bp + q * 4);
        }

        // compute: 4 k-steps of m16n8k8
#pragma unroll
        for (int ks = 0; ks < 4; ks++) {
            int k0 = ks * 8 + tg;
            uint32_t a_f[4][4];
            uint32_t b_f[4][2];
#pragma unroll
            for (int mi = 0; mi < 4; mi++) {
                int m0 = warp_m * 64 + mi * 16 + g;
                a_f[mi][0] = As2[m0][k0];
                a_f[mi][1] = As2[m0 + 8][k0];
                a_f[mi][2] = As2[m0][k0 + 4];
                a_f[mi][3] = As2[m0 + 8][k0 + 4];
            }
#pragma unroll
            for (int ni = 0; ni < 4; ni++) {
                int n0 = warp_n * 32 + ni * 8 + g;
                b_f[ni][0] = Bs[k0][n0];
                b_f[ni][1] = Bs[k0 + 4][n0];
            }
#pragma unroll
            for (int mi = 0; mi < 4; mi++)
#pragma unroll
                for (int ni = 0; ni < 4; ni++)
                    mma_tf32(acc[mi][ni], a_f[mi], b_f[ni]);
        }
        __syncthreads();
    }

    // epilogue: scatter to g_h2 [b][pos][co] with bias
#pragma unroll
    for (int mi = 0; mi < 4; mi++) {
        int m0 = warp_m * 64 + mi * 16 + g;
        int mg0 = by * 128 + m0;
        float bv0 = bias[mg0];
        float bv1 = bias[mg0 + 8];
#pragma unroll
        for (int ni = 0; ni < 4; ni++) {
            int n0 = warp_n * 32 + ni * 8 + 2 * tg;
            int o0 = o2Off[n0], o1 = o2Off[n0 + 1];
            g_h2[o0 + mg0]     = acc[mi][ni][0] + bv0;
            g_h2[o1 + mg0]     = acc[mi][ni][1] + bv0;
            g_h2[o0 + mg0 + 8] = acc[mi][ni][2] + bv1;
            g_h2[o1 + mg0 + 8] = acc[mi][ni][3] + bv1;
        }
    }
}

// ---------------- squash over last spatial axis ----------------
__global__ void squash_conv_kernel() {
    int gid = blockIdx.x * blockDim.x + threadIdx.x;  // 393216 = 256*6*256
    int b = gid / 1536;
    int rem = gid - b * 1536;
    int oy = rem >> 8;
    int co = rem & 255;
    float v[6];
    float n2 = 0.f;
#pragma unroll
    for (int j = 0; j < 6; j++) {
        v[j] = g_h2[(size_t)(b * 36 + oy * 6 + j) * 256 + co];
        n2 += v[j] * v[j];
    }
    float nrm = sqrtf(n2);
    float sc = (n2 / (1.f + n2)) / (nrm + 1e-7f);
    float* q = g_u + (size_t)b * 9216 + co * 36 + oy * 6;
#pragma unroll
    for (int j = 0; j < 6; j++) q[j] = v[j] * sc;
}

// ---------------- u_hat (fp16 out): block = input capsule i ----------------
__global__ __launch_bounds__(320) void uhat_kernel2(const float* __restrict__ Wc) {
    __shared__ float u_s[2048];
    int i = blockIdx.x;
    int t = threadIdx.x;
    int b2 = t / 40;        // 0..7
    int od4 = t - b2 * 40;  // 0..39

    for (int idx = t; idx < 2048; idx += 320) {
        int b = idx >> 3, e = idx & 7;
        u_s[idx] = g_u[(size_t)b * 9216 + i * 8 + e];
    }
    int od0 = od4 * 4;
    int o = od0 >> 4;
    int d0 = od0 & 15;
    const float* wp = Wc + ((size_t)(o * 1152 + i) * 16 + d0) * 8;
    float w[4][8];
#pragma unroll
    for (int q = 0; q < 4; q++) {
        float4 w0 = *(const float4*)(wp + q * 8);
        float4 w1 = *(const float4*)(wp + q * 8 + 4);
        w[q][0] = w0.x; w[q][1] = w0.y; w[q][2] = w0.z; w[q][3] = w0.w;
        w[q][4] = w1.x; w[q][5] = w1.y; w[q][6] = w1.z; w[q][7] = w1.w;
    }
    __syncthreads();
    for (int bo = 0; bo < 32; bo++) {
        int b = bo * 8 + b2;
        float ue[8];
#pragma unroll
        for (int e = 0; e < 8; e++) ue[e] = u_s[b * 8 + e];
        float acc[4];
#pragma unroll
        for (int q = 0; q < 4; q++) {
            float a = 0.f;
#pragma unroll
            for (int e = 0; e < 8; e++) a += w[q][e] * ue[e];
            acc[q] = a;
        }
        __half2 h0 = __floats2half2_rn(acc[0], acc[1]);
        __half2 h1 = __floats2half2_rn(acc[2], acc[3]);
        __half2* dst = (__half2*)(g_uhat + ((size_t)b * 1152 + i) * 160 + od0);
        dst[0] = h0; dst[1] = h1;
    }
}

// ---------------- dynamic routing (3 iters fused), fp16 u_hat ----------------
__device__ __forceinline__ void route_accum(
    const float uh[5], const float* v0s, const float* v1s,
    int p, int lane, float sacc[5]) {
    float c[5];
    float lg[5];
#pragma unroll
    for (int og = 0; og < 5; og++) {
        float tsum = uh[og] * v0s[og * 32 + lane];
        if (p == 2) tsum += uh[og] * v1s[og * 32 + lane];
        tsum += __shfl_xor_sync(0xffffffffu, tsum, 8);
        tsum += __shfl_xor_sync(0xffffffffu, tsum, 4);
        tsum += __shfl_xor_sync(0xffffffffu, tsum, 2);
        tsum += __shfl_xor_sync(0xffffffffu, tsum, 1);
        lg[og] = tsum;
    }
    float m = lg[0];
#pragma unroll
    for (int og = 1; og < 5; og++) m = fmaxf(m, lg[og]);
    m = fmaxf(m, __shfl_xor_sync(0xffffffffu, m, 16));
    float ssum = 0.f;
#pragma unroll
    for (int og = 0; og < 5; og++) { c[og] = expf(lg[og] - m); ssum += c[og]; }
    ssum += __shfl_xor_sync(0xffffffffu, ssum, 16);
    float inv = 1.f / ssum;
#pragma unroll
    for (int og = 0; og < 5; og++) sacc[og] += (c[og] * inv) * uh[og];
}

__global__ __launch_bounds__(256) void routing_kernel(float* __restrict__ out_len) {
    int b = blockIdx.x;
    int tid = threadIdx.x;
    int lane = tid & 31, warp = tid >> 5;

    __shared__ float v0s[160], v1s[160], v2s[160];
    __shared__ float spart[8 * 160];
    __shared__ float sred[160];
    __shared__ float scale_s[10], len_s[10];
    __shared__ int amax_s;

    const __half* base = g_uhat + (size_t)b * 184320;

    for (int p = 0; p < 3; p++) {
        float sacc[5] = {0.f, 0.f, 0.f, 0.f, 0.f};
        for (int ii = warp; ii < 1152; ii += 16) {
            const __half* pA = base + ii * 160;
            const __half* pB = base + (ii + 8) * 160;
            float uhA[5], uhB[5];
#pragma unroll
            for (int og = 0; og < 5; og++) uhA[og] = __half2float(pA[og * 32 + lane]);
#pragma unroll
            for (int og = 0; og < 5; og++) uhB[og] = __half2float(pB[og * 32 + lane]);
            if (p == 0) {
#pragma unroll
                for (int og = 0; og < 5; og++) sacc[og] += 0.1f * (uhA[og] + uhB[og]);
            } else {
                route_accum(uhA, v0s, v1s, p, lane, sacc);
                route_accum(uhB, v0s, v1s, p, lane, sacc);
            }
        }
#pragma unroll
        for (int og = 0; og < 5; og++) spart[warp * 160 + og * 32 + lane] = sacc[og];
        __syncthreads();
        if (tid < 160) {
            float tot = 0.f;
#pragma unroll
            for (int w = 0; w < 8; w++) tot += spart[w * 160 + tid];
            sred[tid] = tot;
        }
        __syncthreads();
        if (tid < 10) {
            float n2 = 0.f;
#pragma unroll
            for (int d = 0; d < 16; d++) { float xv = sred[tid * 16 + d]; n2 += xv * xv; }
            float nrm = sqrtf(n2);
            scale_s[tid] = (n2 / (1.f + n2)) / (nrm + 1e-7f);
            if (p == 2) len_s[tid] = (n2 / (1.f + n2)) * (nrm / (nrm + 1e-7f));
        }
        __syncthreads();
        float* vdst = (p == 0) ? v0s : ((p == 1) ? v1s : v2s);
        if (tid < 160) vdst[tid] = sred[tid] * scale_s[tid >> 4];
        __syncthreads();
    }

    if (tid == 0) {
        int bi = 0;
        float best = len_s[0];
#pragma unroll
        for (int o = 1; o < 10; o++)
            if (len_s[o] > best) { best = len_s[o]; bi = o; }
        amax_s = bi;
    }
    if (tid < 10) out_len[b * 10 + tid] = len_s[tid];
    __syncthreads();
    if (tid < 160) g_masked[b * 160 + tid] = ((tid >> 4) == amax_s) ? v2s[tid] : 0.f;
}

// ---------------- decoder GEMM (64x64x16 tile, 4x4 micro), epilogue fused ----------------
template <int EPI>
__global__ __launch_bounds__(256) void gemm_epi(
    const float* __restrict__ A, const float* __restrict__ W,
    const float* __restrict__ bias, float* __restrict__ C,
    int M, int N, int K) {
    __shared__ float As[16][64];
    __shared__ float Bs[16][64];
    int t = threadIdx.x;
    int bx = blockIdx.x, by = blockIdx.y;
    int arow = t >> 2, ak = (t & 3) * 4;
    int bkr = t >> 4, bnc = (t & 15) * 4;
    int tx = t & 15, ty = t >> 4;

    float acc[4][4];
#pragma unroll
    for (int i = 0; i < 4; i++)
#pragma unroll
        for (int j = 0; j < 4; j++) acc[i][j] = 0.f;

    for (int kk = 0; kk < K; kk += 16) {
        float4 av = *(const float4*)(A + (size_t)(by * 64 + arow) * K + kk + ak);
        int n0 = bx * 64 + bnc;
        float4 bv = make_float4(0.f, 0.f, 0.f, 0.f);
        if (n0 < N) bv = *(const float4*)(W + (size_t)(kk + bkr) * N + n0);
        As[ak + 0][arow] = av.x; As[ak + 1][arow] = av.y;
        As[ak + 2][arow] = av.z; As[ak + 3][arow] = av.w;
        *(float4*)&Bs[bkr][bnc] = bv;
        __syncthreads();
#pragma unroll
        for (int kr = 0; kr < 16; kr++) {
            float af[4], bf[4];
            *(float4*)af = *(const float4*)&As[kr][ty * 4];
            *(float4*)bf = *(const float4*)&Bs[kr][tx * 4];
#pragma unroll
            for (int mi = 0; mi < 4; mi++)
#pragma unroll
                for (int ni = 0; ni < 4; ni++) acc[mi][ni] += af[mi] * bf[ni];
        }
        __syncthreads();
    }

#pragma unroll
    for (int mi = 0; mi < 4; mi++) {
        int m = by * 64 + ty * 4 + mi;
#pragma unroll
        for (int ni = 0; ni < 4; ni++) {
            int n = bx * 64 + tx * 4 + ni;
            if (n < N) {
                float v = acc[mi][ni] + bias[n];
                if (EPI == 1) v = fmaxf(v, 0.f);
                if (EPI == 2) v = 1.f / (1.f + expf(-v));
                C[(size_t)m * N + n] = v;
            }
        }
    }
}

// ---------------- launch ----------------
extern "C" void kernel_launch(void* const* d_in, const int* in_sizes, int n_in,
                              void* d_out, int out_size) {
    const float* x     = (const float*)d_in[0];
    const float* c1w   = (const float*)d_in[1];
    const float* c1b   = (const float*)d_in[2];
    const float* c2w   = (const float*)d_in[3];
    const float* c2b   = (const float*)d_in[4];
    const float* Wcaps = (const float*)d_in[5];
    const float* dw1   = (const float*)d_in[6];
    const float* db1   = (const float*)d_in[7];
    const float* dw2   = (const float*)d_in[8];
    const float* db2   = (const float*)d_in[9];
    const float* dw3   = (const float*)d_in[10];
    const float* db3   = (const float*)d_in[11];
    float* out = (float*)d_out;

    float* g_d1_ptr; cudaGetSymbolAddress((void**)&g_d1_ptr, g_d1);
    float* g_d2_ptr; cudaGetSymbolAddress((void**)&g_d2_ptr, g_d2);
    float* g_m_ptr;  cudaGetSymbolAddress((void**)&g_m_ptr, g_masked);

    cudaFuncSetAttribute(wtrans_kernel, cudaFuncAttributeMaxDynamicSharedMemorySize,
                         20736 * 4);

    wtrans_kernel<<<256, 256, 20736 * 4>>>(c2w);
    conv1_kernel<<<dim3(256, 2), 128>>>(x, c1w, c1b);
    conv2_mma<<<dim3(72, 2), 256>>>(c2b);
    squash_conv_kernel<<<1536, 256>>>();
    uhat_kernel2<<<1152, 320>>>(Wcaps);
    routing_kernel<<<256, 256>>>(out);
    gemm_epi<1><<<dim3(8, 4), 256>>>(g_m_ptr, dw1, db1, g_d1_ptr, 256, 512, 160);
    gemm_epi<1><<<dim3(16, 4), 256>>>(g_d1_ptr, dw2, db2, g_d2_ptr, 256, 1024, 512);
    gemm_epi<2><<<dim3(13, 4), 256>>>(g_d2_ptr, dw3, db3, out + 2560, 256, 784, 1024);
}

// round 6
// speedup vs baseline: 2.9538x; 1.3023x over previous
#include <cuda_runtime.h>
#include <cuda_fp16.h>
#include <math.h>
#include <stdint.h>

// ---------------- scratch (device globals: allocation-free contract) ----------------
__device__ float g_h1[256 * 400 * 256];             // conv1 out [b][y][x][ci] (tf32-rounded)
__device__ float g_wt[256 * 20736];                 // conv2 W   [co][ky*9+kx][ci] (tf32-rounded)
__device__ float g_h2[256 * 9216];                  // conv2 out [b][pos][co]
__device__ float g_u[256 * 9216];                   // squashed  [b][co*36+pos]
__device__ __half g_uhat[(size_t)256 * 1152 * 160]; // u_hat     [b][i][o][d] fp16
__device__ float g_masked[256 * 160];
__device__ float g_d1[256 * 512];
__device__ float g_d2[256 * 1024];

__device__ __forceinline__ uint32_t f2tf(float x) {
    uint32_t o;
    asm("cvt.rna.tf32.f32 %0, %1;" : "=r"(o) : "f"(x));
    return o;
}
__device__ __forceinline__ void mma_tf32(float* c, const uint32_t* a, const uint32_t* b) {
    asm volatile(
        "mma.sync.aligned.m16n8k8.row.col.f32.tf32.tf32.f32 "
        "{%0,%1,%2,%3}, {%4,%5,%6,%7}, {%8,%9}, {%0,%1,%2,%3};"
        : "+f"(c[0]), "+f"(c[1]), "+f"(c[2]), "+f"(c[3])
        : "r"(a[0]), "r"(a[1]), "r"(a[2]), "r"(a[3]), "r"(b[0]), "r"(b[1]));
}
__device__ __forceinline__ void cp16(uint32_t smem_dst, const void* gsrc) {
    asm volatile("cp.async.cg.shared.global [%0], [%1], 16;" :: "r"(smem_dst), "l"(gsrc));
}
#define CP_COMMIT() asm volatile("cp.async.commit_group;")
#define CP_WAIT2()  asm volatile("cp.async.wait_group 2;")

// ---------------- conv1: [256,1,28,28] -> [b][y][x][co] channel-last, tf32-rounded ----------------
__global__ __launch_bounds__(128) void conv1_kernel(
    const float* __restrict__ x, const float* __restrict__ w,
    const float* __restrict__ bias) {
    __shared__ float xs[784];
    __shared__ float ws[128 * 81];
    int b = blockIdx.x;
    int cb = blockIdx.y * 128;
    int t = threadIdx.x;

    for (int idx = t; idx < 784; idx += 128) xs[idx] = x[b * 784 + idx];
    for (int idx = t; idx < 128 * 81; idx += 128) ws[idx] = w[cb * 81 + idx];
    __syncthreads();

    int co = cb + t;
    float bv = bias[co];
    float* outp = g_h1 + (size_t)b * 400 * 256 + co;

    for (int oy = 0; oy < 20; oy++) {
        float acc[20];
#pragma unroll
        for (int j = 0; j < 20; j++) acc[j] = bv;
        for (int ky = 0; ky < 9; ky++) {
            float xr[28];
#pragma unroll
            for (int j = 0; j < 28; j++) xr[j] = xs[(oy + ky) * 28 + j];
#pragma unroll
            for (int kx = 0; kx < 9; kx++) {
                float wv = ws[t * 81 + ky * 9 + kx];
#pragma unroll
                for (int ox = 0; ox < 20; ox++) acc[ox] += wv * xr[ox + kx];
            }
        }
#pragma unroll
        for (int ox = 0; ox < 20; ox++)
            outp[(oy * 20 + ox) * 256] = __uint_as_float(f2tf(acc[ox]));
    }
}

// ---------------- conv2 weight transpose + tf32 round ----------------
__global__ void wtrans_kernel(const float* __restrict__ Wc) {
    extern __shared__ float s[];  // 20736 floats
    int co = blockIdx.x;
    int t = threadIdx.x;
    const float* src = Wc + (size_t)co * 20736;
    for (int idx = t; idx < 20736; idx += 256) s[idx] = src[idx];
    __syncthreads();
    float* dst = g_wt + (size_t)co * 20736;
    for (int idx = t; idx < 20736; idx += 256) {
        int j = idx >> 8, ci = idx & 255;
        dst[idx] = __uint_as_float(f2tf(s[ci * 81 + j]));
    }
}

// ---------------- conv2: tf32 mma.sync, 3-stage cp.async pipeline ----------------
// D[m=co(128), n=(b,pos)(128)]; K = 81*256 ordered (ky,kx,ci); k-tile 32.
#define LDT 36
#define STAGE_F (128 * LDT)          // floats per (A or B) stage
#define SM_DYN (6 * STAGE_F * 4)     // 3 stages x (A+B) = 110592 bytes

__global__ __launch_bounds__(256) void conv2_mma(const float* __restrict__ bias) {
    extern __shared__ float smem[];
    float* Abuf = smem;                 // [3][128][LDT]
    float* Bbuf = smem + 3 * STAGE_F;   // [3][128][LDT]
    __shared__ int nOffT[128];
    __shared__ int o2Off[128];

    int t = threadIdx.x;
    int bx = blockIdx.x, by = blockIdx.y;
    int wid = t >> 5, lane = t & 31;
    int g = lane >> 2, tg = lane & 3;
    int warp_m = wid >> 2, warp_n = wid & 3;

    if (t < 128) {
        int n = bx * 128 + t;
        int b = n / 36, pos = n - b * 36;
        int oy = pos / 6, ox = pos - oy * 6;
        nOffT[t] = (b * 400 + oy * 40 + ox * 2) * 256;
        o2Off[t] = (b * 36 + pos) * 256;
    }
    __syncthreads();

    // loader mapping: chunk = t + 256q -> row = (t>>3)+32q, part = t&7
    int lrow = t >> 3, lpart = (t & 7) * 4;
    const float* abase = g_wt + (size_t)(by * 128) * 20736;

    const int ITERS = 648;  // 81 * 8

    auto issue = [&](int ii) {
        int s = ii % 3;
        int kxy = ii >> 3, cib = (ii & 7) << 5;
        int ky = kxy / 9, kx = kxy - ky * 9;
        int hoff = (ky * 20 + kx) * 256 + cib;
        float* As_s = Abuf + s * STAGE_F;
        float* Bs_s = Bbuf + s * STAGE_F;
#pragma unroll
        for (int q = 0; q < 4; q++) {
            int row = lrow + 32 * q;
            uint32_t da = (uint32_t)__cvta_generic_to_shared(As_s + row * LDT + lpart);
            cp16(da, abase + (size_t)row * 20736 + kxy * 256 + cib + lpart);
            uint32_t db = (uint32_t)__cvta_generic_to_shared(Bs_s + row * LDT + lpart);
            cp16(db, g_h1 + nOffT[row] + hoff + lpart);
        }
        CP_COMMIT();
    };

    issue(0); issue(1); issue(2);

    float acc[4][4][4];
#pragma unroll
    for (int mi = 0; mi < 4; mi++)
#pragma unroll
        for (int ni = 0; ni < 4; ni++)
#pragma unroll
            for (int r = 0; r < 4; r++) acc[mi][ni][r] = 0.f;

    for (int i = 0; i < ITERS; i++) {
        CP_WAIT2();
        __syncthreads();

        const uint32_t* As_s = (const uint32_t*)(Abuf + (i % 3) * STAGE_F);
        const uint32_t* Bs_s = (const uint32_t*)(Bbuf + (i % 3) * STAGE_F);

#pragma unroll
        for (int ks = 0; ks < 4; ks++) {
            int k0 = ks * 8 + tg;
            uint32_t a_f[4][4];
            uint32_t b_f[4][2];
#pragma unroll
            for (int mi = 0; mi < 4; mi++) {
                int m0 = warp_m * 64 + mi * 16 + g;
                a_f[mi][0] = As_s[m0 * LDT + k0];
                a_f[mi][1] = As_s[(m0 + 8) * LDT + k0];
                a_f[mi][2] = As_s[m0 * LDT + k0 + 4];
                a_f[mi][3] = As_s[(m0 + 8) * LDT + k0 + 4];
            }
#pragma unroll
            for (int ni = 0; ni < 4; ni++) {
                int n0 = warp_n * 32 + ni * 8 + g;
                b_f[ni][0] = Bs_s[n0 * LDT + k0];
                b_f[ni][1] = Bs_s[n0 * LDT + k0 + 4];
            }
#pragma unroll
            for (int mi = 0; mi < 4; mi++)
#pragma unroll
                for (int ni = 0; ni < 4; ni++)
                    mma_tf32(acc[mi][ni], a_f[mi], b_f[ni]);
        }
        __syncthreads();

        if (i + 3 < ITERS) issue(i + 3);
        else CP_COMMIT();
    }

    // epilogue: scatter to g_h2 [b][pos][co] with bias
#pragma unroll
    for (int mi = 0; mi < 4; mi++) {
        int m0 = warp_m * 64 + mi * 16 + g;
        int mg0 = by * 128 + m0;
        float bv0 = bias[mg0];
        float bv1 = bias[mg0 + 8];
#pragma unroll
        for (int ni = 0; ni < 4; ni++) {
            int n0 = warp_n * 32 + ni * 8 + 2 * tg;
            int o0 = o2Off[n0], o1 = o2Off[n0 + 1];
            g_h2[o0 + mg0]     = acc[mi][ni][0] + bv0;
            g_h2[o1 + mg0]     = acc[mi][ni][1] + bv0;
            g_h2[o0 + mg0 + 8] = acc[mi][ni][2] + bv1;
            g_h2[o1 + mg0 + 8] = acc[mi][ni][3] + bv1;
        }
    }
}

// ---------------- squash over last spatial axis ----------------
__global__ void squash_conv_kernel() {
    int gid = blockIdx.x * blockDim.x + threadIdx.x;  // 393216
    int b = gid / 1536;
    int rem = gid - b * 1536;
    int oy = rem >> 8;
    int co = rem & 255;
    float v[6];
    float n2 = 0.f;
#pragma unroll
    for (int j = 0; j < 6; j++) {
        v[j] = g_h2[(size_t)(b * 36 + oy * 6 + j) * 256 + co];
        n2 += v[j] * v[j];
    }
    float nrm = sqrtf(n2);
    float sc = (n2 / (1.f + n2)) / (nrm + 1e-7f);
    float* q = g_u + (size_t)b * 9216 + co * 36 + oy * 6;
#pragma unroll
    for (int j = 0; j < 6; j++) q[j] = v[j] * sc;
}

// ---------------- u_hat (fp16 out): block = input capsule i ----------------
__global__ __launch_bounds__(320) void uhat_kernel2(const float* __restrict__ Wc) {
    __shared__ float u_s[2048];
    int i = blockIdx.x;
    int t = threadIdx.x;
    int b2 = t / 40;
    int od4 = t - b2 * 40;

    for (int idx = t; idx < 2048; idx += 320) {
        int b = idx >> 3, e = idx & 7;
        u_s[idx] = g_u[(size_t)b * 9216 + i * 8 + e];
    }
    int od0 = od4 * 4;
    int o = od0 >> 4;
    int d0 = od0 & 15;
    const float* wp = Wc + ((size_t)(o * 1152 + i) * 16 + d0) * 8;
    float w[4][8];
#pragma unroll
    for (int q = 0; q < 4; q++) {
        float4 w0 = *(const float4*)(wp + q * 8);
        float4 w1 = *(const float4*)(wp + q * 8 + 4);
        w[q][0] = w0.x; w[q][1] = w0.y; w[q][2] = w0.z; w[q][3] = w0.w;
        w[q][4] = w1.x; w[q][5] = w1.y; w[q][6] = w1.z; w[q][7] = w1.w;
    }
    __syncthreads();
    for (int bo = 0; bo < 32; bo++) {
        int b = bo * 8 + b2;
        float ue[8];
#pragma unroll
        for (int e = 0; e < 8; e++) ue[e] = u_s[b * 8 + e];
        float acc[4];
#pragma unroll
        for (int q = 0; q < 4; q++) {
            float a = 0.f;
#pragma unroll
            for (int e = 0; e < 8; e++) a += w[q][e] * ue[e];
            acc[q] = a;
        }
        __half2 h0 = __floats2half2_rn(acc[0], acc[1]);
        __half2 h1 = __floats2half2_rn(acc[2], acc[3]);
        __half2* dst = (__half2*)(g_uhat + ((size_t)b * 1152 + i) * 160 + od0);
        dst[0] = h0; dst[1] = h1;
    }
}

// ---------------- dynamic routing (3 iters fused), fp16 u_hat ----------------
__device__ __forceinline__ void route_accum(
    const float uh[5], const float* v0s, const float* v1s,
    int p, int lane, float sacc[5]) {
    float c[5];
    float lg[5];
#pragma unroll
    for (int og = 0; og < 5; og++) {
        float tsum = uh[og] * v0s[og * 32 + lane];
        if (p == 2) tsum += uh[og] * v1s[og * 32 + lane];
        tsum += __shfl_xor_sync(0xffffffffu, tsum, 8);
        tsum += __shfl_xor_sync(0xffffffffu, tsum, 4);
        tsum += __shfl_xor_sync(0xffffffffu, tsum, 2);
        tsum += __shfl_xor_sync(0xffffffffu, tsum, 1);
        lg[og] = tsum;
    }
    float m = lg[0];
#pragma unroll
    for (int og = 1; og < 5; og++) m = fmaxf(m, lg[og]);
    m = fmaxf(m, __shfl_xor_sync(0xffffffffu, m, 16));
    float ssum = 0.f;
#pragma unroll
    for (int og = 0; og < 5; og++) { c[og] = expf(lg[og] - m); ssum += c[og]; }
    ssum += __shfl_xor_sync(0xffffffffu, ssum, 16);
    float inv = 1.f / ssum;
#pragma unroll
    for (int og = 0; og < 5; og++) sacc[og] += (c[og] * inv) * uh[og];
}

__global__ __launch_bounds__(256) void routing_kernel(float* __restrict__ out_len) {
    int b = blockIdx.x;
    int tid = threadIdx.x;
    int lane = tid & 31, warp = tid >> 5;

    __shared__ float v0s[160], v1s[160], v2s[160];
    __shared__ float spart[8 * 160];
    __shared__ float sred[160];
    __shared__ float scale_s[10], len_s[10];
    __shared__ int amax_s;

    const __half* base = g_uhat + (size_t)b * 184320;

    for (int p = 0; p < 3; p++) {
        float sacc[5] = {0.f, 0.f, 0.f, 0.f, 0.f};
        for (int ii = warp; ii < 1152; ii += 16) {
            const __half* pA = base + ii * 160;
            const __half* pB = base + (ii + 8) * 160;
            float uhA[5], uhB[5];
#pragma unroll
            for (int og = 0; og < 5; og++) uhA[og] = __half2float(pA[og * 32 + lane]);
#pragma unroll
            for (int og = 0; og < 5; og++) uhB[og] = __half2float(pB[og * 32 + lane]);
            if (p == 0) {
#pragma unroll
                for (int og = 0; og < 5; og++) sacc[og] += 0.1f * (uhA[og] + uhB[og]);
            } else {
                route_accum(uhA, v0s, v1s, p, lane, sacc);
                route_accum(uhB, v0s, v1s, p, lane, sacc);
            }
        }
#pragma unroll
        for (int og = 0; og < 5; og++) spart[warp * 160 + og * 32 + lane] = sacc[og];
        __syncthreads();
        if (tid < 160) {
            float tot = 0.f;
#pragma unroll
            for (int w = 0; w < 8; w++) tot += spart[w * 160 + tid];
            sred[tid] = tot;
        }
        __syncthreads();
        if (tid < 10) {
            float n2 = 0.f;
#pragma unroll
            for (int d = 0; d < 16; d++) { float xv = sred[tid * 16 + d]; n2 += xv * xv; }
            float nrm = sqrtf(n2);
            scale_s[tid] = (n2 / (1.f + n2)) / (nrm + 1e-7f);
            if (p == 2) len_s[tid] = (n2 / (1.f + n2)) * (nrm / (nrm + 1e-7f));
        }
        __syncthreads();
        float* vdst = (p == 0) ? v0s : ((p == 1) ? v1s : v2s);
        if (tid < 160) vdst[tid] = sred[tid] * scale_s[tid >> 4];
        __syncthreads();
    }

    if (tid == 0) {
        int bi = 0;
        float best = len_s[0];
#pragma unroll
        for (int o = 1; o < 10; o++)
            if (len_s[o] > best) { best = len_s[o]; bi = o; }
        amax_s = bi;
    }
    if (tid < 10) out_len[b * 10 + tid] = len_s[tid];
    __syncthreads();
    if (tid < 160) g_masked[b * 160 + tid] = ((tid >> 4) == amax_s) ? v2s[tid] : 0.f;
}

// ---------------- decoder GEMM (64x64x16 tile, 4x4 micro), epilogue fused ----------------
template <int EPI>
__global__ __launch_bounds__(256) void gemm_epi(
    const float* __restrict__ A, const float* __restrict__ W,
    const float* __restrict__ bias, float* __restrict__ C,
    int M, int N, int K) {
    __shared__ float As[16][64];
    __shared__ float Bs[16][64];
    int t = threadIdx.x;
    int bx = blockIdx.x, by = blockIdx.y;
    int arow = t >> 2, ak = (t & 3) * 4;
    int bkr = t >> 4, bnc = (t & 15) * 4;
    int tx = t & 15, ty = t >> 4;

    float acc[4][4];
#pragma unroll
    for (int i = 0; i < 4; i++)
#pragma unroll
        for (int j = 0; j < 4; j++) acc[i][j] = 0.f;

    for (int kk = 0; kk < K; kk += 16) {
        float4 av = *(const float4*)(A + (size_t)(by * 64 + arow) * K + kk + ak);
        int n0 = bx * 64 + bnc;
        float4 bv = make_float4(0.f, 0.f, 0.f, 0.f);
        if (n0 < N) bv = *(const float4*)(W + (size_t)(kk + bkr) * N + n0);
        As[ak + 0][arow] = av.x; As[ak + 1][arow] = av.y;
        As[ak + 2][arow] = av.z; As[ak + 3][arow] = av.w;
        *(float4*)&Bs[bkr][bnc] = bv;
        __syncthreads();
#pragma unroll
        for (int kr = 0; kr < 16; kr++) {
            float af[4], bf[4];
            *(float4*)af = *(const float4*)&As[kr][ty * 4];
            *(float4*)bf = *(const float4*)&Bs[kr][tx * 4];
#pragma unroll
            for (int mi = 0; mi < 4; mi++)
#pragma unroll
                for (int ni = 0; ni < 4; ni++) acc[mi][ni] += af[mi] * bf[ni];
        }
        __syncthreads();
    }

#pragma unroll
    for (int mi = 0; mi < 4; mi++) {
        int m = by * 64 + ty * 4 + mi;
#pragma unroll
        for (int ni = 0; ni < 4; ni++) {
            int n = bx * 64 + tx * 4 + ni;
            if (n < N) {
                float v = acc[mi][ni] + bias[n];
                if (EPI == 1) v = fmaxf(v, 0.f);
                if (EPI == 2) v = 1.f / (1.f + expf(-v));
                C[(size_t)m * N + n] = v;
            }
        }
    }
}

// ---------------- launch ----------------
extern "C" void kernel_launch(void* const* d_in, const int* in_sizes, int n_in,
                              void* d_out, int out_size) {
    const float* x     = (const float*)d_in[0];
    const float* c1w   = (const float*)d_in[1];
    const float* c1b   = (const float*)d_in[2];
    const float* c2w   = (const float*)d_in[3];
    const float* c2b   = (const float*)d_in[4];
    const float* Wcaps = (const float*)d_in[5];
    const float* dw1   = (const float*)d_in[6];
    const float* db1   = (const float*)d_in[7];
    const float* dw2   = (const float*)d_in[8];
    const float* db2   = (const float*)d_in[9];
    const float* dw3   = (const float*)d_in[10];
    const float* db3   = (const float*)d_in[11];
    float* out = (float*)d_out;

    float* g_d1_ptr; cudaGetSymbolAddress((void**)&g_d1_ptr, g_d1);
    float* g_d2_ptr; cudaGetSymbolAddress((void**)&g_d2_ptr, g_d2);
    float* g_m_ptr;  cudaGetSymbolAddress((void**)&g_m_ptr, g_masked);

    cudaFuncSetAttribute(wtrans_kernel, cudaFuncAttributeMaxDynamicSharedMemorySize,
                         20736 * 4);
    cudaFuncSetAttribute(conv2_mma, cudaFuncAttributeMaxDynamicSharedMemorySize, SM_DYN);

    wtrans_kernel<<<256, 256, 20736 * 4>>>(c2w);
    conv1_kernel<<<dim3(256, 2), 128>>>(x, c1w, c1b);
    conv2_mma<<<dim3(72, 2), 256, SM_DYN>>>(c2b);
    squash_conv_kernel<<<1536, 256>>>();
    uhat_kernel2<<<1152, 320>>>(Wcaps);
    routing_kernel<<<256, 256>>>(out);
    gemm_epi<1><<<dim3(8, 4), 256>>>(g_m_ptr, dw1, db1, g_d1_ptr, 256, 512, 160);
    gemm_epi<1><<<dim3(16, 4), 256>>>(g_d1_ptr, dw2, db2, g_d2_ptr, 256, 1024, 512);
    gemm_epi<2><<<dim3(13, 4), 256>>>(g_d2_ptr, dw3, db3, out + 2560, 256, 784, 1024);
}

// round 7
// speedup vs baseline: 3.5693x; 1.2084x over previous
#include <cuda_runtime.h>
#include <cuda_fp16.h>
#include <math.h>
#include <stdint.h>

// ---------------- scratch (device globals: allocation-free contract) ----------------
__device__ __half g_h1[256 * 400 * 256];            // conv1 out [b][y][x][ci] fp16
__device__ __half g_wt[256 * 20736];                // conv2 W   [co][ky*9+kx][ci] fp16
__device__ float g_h2[256 * 9216];                  // conv2 out [b][pos][co]
__device__ float g_u[256 * 9216];                   // squashed  [b][co*36+pos]
__device__ __half g_uhat[(size_t)256 * 1152 * 160]; // u_hat     [b][i][o][d] fp16
__device__ float g_masked[256 * 160];
__device__ float g_d1[256 * 512];
__device__ float g_d2[256 * 1024];

__device__ __forceinline__ void mma_f16(float* c, const uint32_t* a, const uint32_t* b) {
    asm volatile(
        "mma.sync.aligned.m16n8k16.row.col.f32.f16.f16.f32 "
        "{%0,%1,%2,%3}, {%4,%5,%6,%7}, {%8,%9}, {%0,%1,%2,%3};"
        : "+f"(c[0]), "+f"(c[1]), "+f"(c[2]), "+f"(c[3])
        : "r"(a[0]), "r"(a[1]), "r"(a[2]), "r"(a[3]), "r"(b[0]), "r"(b[1]));
}
__device__ __forceinline__ void cp16(uint32_t smem_dst, const void* gsrc) {
    asm volatile("cp.async.cg.shared.global [%0], [%1], 16;" :: "r"(smem_dst), "l"(gsrc));
}
#define CP_COMMIT() asm volatile("cp.async.commit_group;")
#define CP_WAIT2()  asm volatile("cp.async.wait_group 2;")

// ---------------- conv1: [256,1,28,28] -> [b][y][x][co] channel-last fp16 ----------------
__global__ __launch_bounds__(128) void conv1_kernel(
    const float* __restrict__ x, const float* __restrict__ w,
    const float* __restrict__ bias) {
    __shared__ float xs[784];
    __shared__ float ws[128 * 81];
    int b = blockIdx.x;
    int cb = blockIdx.y * 128;
    int t = threadIdx.x;

    for (int idx = t; idx < 784; idx += 128) xs[idx] = x[b * 784 + idx];
    for (int idx = t; idx < 128 * 81; idx += 128) ws[idx] = w[cb * 81 + idx];
    __syncthreads();

    int co = cb + t;
    float bv = bias[co];
    __half* outp = g_h1 + (size_t)b * 400 * 256 + co;

    for (int oy = 0; oy < 20; oy++) {
        float acc[20];
#pragma unroll
        for (int j = 0; j < 20; j++) acc[j] = bv;
        for (int ky = 0; ky < 9; ky++) {
            float xr[28];
#pragma unroll
            for (int j = 0; j < 28; j++) xr[j] = xs[(oy + ky) * 28 + j];
#pragma unroll
            for (int kx = 0; kx < 9; kx++) {
                float wv = ws[t * 81 + ky * 9 + kx];
#pragma unroll
                for (int ox = 0; ox < 20; ox++) acc[ox] += wv * xr[ox + kx];
            }
        }
#pragma unroll
        for (int ox = 0; ox < 20; ox++)
            outp[(oy * 20 + ox) * 256] = __float2half_rn(acc[ox]);
    }
}

// ---------------- conv2 weight transpose -> fp16 [co][ky*9+kx][ci] ----------------
__global__ void wtrans_kernel(const float* __restrict__ Wc) {
    extern __shared__ float s[];  // 20736 floats
    int co = blockIdx.x;
    int t = threadIdx.x;
    const float* src = Wc + (size_t)co * 20736;
    for (int idx = t; idx < 20736; idx += 256) s[idx] = src[idx];
    __syncthreads();
    __half* dst = g_wt + (size_t)co * 20736;
    for (int idx = t; idx < 20736; idx += 256) {
        int j = idx >> 8, ci = idx & 255;
        dst[idx] = __float2half_rn(s[ci * 81 + j]);
    }
}

// ---------------- conv2: fp16 mma.sync m16n8k16, 3-stage cp.async, k-tile 64 ----------------
#define LDT 72                       // halfs per row (64 + 8 pad); 144B, 16B-aligned stride
#define LDW 36                       // b32 words per row
#define STAGE_H (128 * LDT)          // halfs per (A or B) stage
#define SM_DYN (6 * STAGE_H * 2)     // 3 stages x (A+B) = 110592 bytes

__global__ __launch_bounds__(256) void conv2_mma(const float* __restrict__ bias) {
    extern __shared__ __half smemh[];
    __half* Abuf = smemh;                 // [3][128][LDT]
    __half* Bbuf = smemh + 3 * STAGE_H;   // [3][128][LDT]
    __shared__ int nOffT[128];
    __shared__ int o2Off[128];

    int t = threadIdx.x;
    int bx = blockIdx.x, by = blockIdx.y;
    int wid = t >> 5, lane = t & 31;
    int g = lane >> 2, tg = lane & 3;
    int warp_m = wid >> 2, warp_n = wid & 3;

    if (t < 128) {
        int n = bx * 128 + t;
        int b = n / 36, pos = n - b * 36;
        int oy = pos / 6, ox = pos - oy * 6;
        nOffT[t] = (b * 400 + oy * 40 + ox * 2) * 256;   // halfs into g_h1
        o2Off[t] = (b * 36 + pos) * 256;                 // into g_h2
    }
    __syncthreads();

    // loader: thread t -> row t>>1 (0..127), half-offset (t&1)*32 within 64-k tile
    int lrow = t >> 1, lpart = (t & 1) * 32;
    const __half* abase = g_wt + (size_t)(by * 128) * 20736;

    const int ITERS = 324;  // 81 * 4 (k-tile 64)

    auto issue = [&](int ii) {
        int s = ii % 3;
        int kxy = ii >> 2, cib = (ii & 3) << 6;
        int ky = kxy / 9, kx = kxy - ky * 9;
        int hoff = (ky * 20 + kx) * 256 + cib;
        __half* As_s = Abuf + s * STAGE_H;
        __half* Bs_s = Bbuf + s * STAGE_H;
        const __half* ga = abase + (size_t)lrow * 20736 + kxy * 256 + cib + lpart;
        const __half* gb = g_h1 + nOffT[lrow] + hoff + lpart;
        uint32_t da = (uint32_t)__cvta_generic_to_shared(As_s + lrow * LDT + lpart);
        uint32_t db = (uint32_t)__cvta_generic_to_shared(Bs_s + lrow * LDT + lpart);
#pragma unroll
        for (int q = 0; q < 4; q++) {
            cp16(da + q * 16, ga + q * 8);
            cp16(db + q * 16, gb + q * 8);
        }
        CP_COMMIT();
    };

    issue(0); issue(1); issue(2);

    float acc[4][4][4];
#pragma unroll
    for (int mi = 0; mi < 4; mi++)
#pragma unroll
        for (int ni = 0; ni < 4; ni++)
#pragma unroll
            for (int r = 0; r < 4; r++) acc[mi][ni][r] = 0.f;

    for (int i = 0; i < ITERS; i++) {
        CP_WAIT2();
        __syncthreads();

        const uint32_t* As_w = (const uint32_t*)(Abuf + (i % 3) * STAGE_H);
        const uint32_t* Bs_w = (const uint32_t*)(Bbuf + (i % 3) * STAGE_H);

#pragma unroll
        for (int ks = 0; ks < 4; ks++) {
            int kw = ks * 8 + tg;  // b32 word offset within row
            uint32_t a_f[4][4];
            uint32_t b_f[4][2];
#pragma unroll
            for (int mi = 0; mi < 4; mi++) {
                int m0 = warp_m * 64 + mi * 16 + g;
                a_f[mi][0] = As_w[m0 * LDW + kw];
                a_f[mi][1] = As_w[(m0 + 8) * LDW + kw];
                a_f[mi][2] = As_w[m0 * LDW + kw + 4];
                a_f[mi][3] = As_w[(m0 + 8) * LDW + kw + 4];
            }
#pragma unroll
            for (int ni = 0; ni < 4; ni++) {
                int n0 = warp_n * 32 + ni * 8 + g;
                b_f[ni][0] = Bs_w[n0 * LDW + kw];
                b_f[ni][1] = Bs_w[n0 * LDW + kw + 4];
            }
#pragma unroll
            for (int mi = 0; mi < 4; mi++)
#pragma unroll
                for (int ni = 0; ni < 4; ni++)
                    mma_f16(acc[mi][ni], a_f[mi], b_f[ni]);
        }
        __syncthreads();

        if (i + 3 < ITERS) issue(i + 3);
        else CP_COMMIT();
    }

    // epilogue: scatter to g_h2 [b][pos][co] with bias
#pragma unroll
    for (int mi = 0; mi < 4; mi++) {
        int m0 = warp_m * 64 + mi * 16 + g;
        int mg0 = by * 128 + m0;
        float bv0 = bias[mg0];
        float bv1 = bias[mg0 + 8];
#pragma unroll
        for (int ni = 0; ni < 4; ni++) {
            int n0 = warp_n * 32 + ni * 8 + 2 * tg;
            int o0 = o2Off[n0], o1 = o2Off[n0 + 1];
            g_h2[o0 + mg0]     = acc[mi][ni][0] + bv0;
            g_h2[o1 + mg0]     = acc[mi][ni][1] + bv0;
            g_h2[o0 + mg0 + 8] = acc[mi][ni][2] + bv1;
            g_h2[o1 + mg0 + 8] = acc[mi][ni][3] + bv1;
        }
    }
}

// ---------------- squash over last spatial axis ----------------
__global__ void squash_conv_kernel() {
    int gid = blockIdx.x * blockDim.x + threadIdx.x;  // 393216
    int b = gid / 1536;
    int rem = gid - b * 1536;
    int oy = rem >> 8;
    int co = rem & 255;
    float v[6];
    float n2 = 0.f;
#pragma unroll
    for (int j = 0; j < 6; j++) {
        v[j] = g_h2[(size_t)(b * 36 + oy * 6 + j) * 256 + co];
        n2 += v[j] * v[j];
    }
    float nrm = sqrtf(n2);
    float sc = (n2 / (1.f + n2)) / (nrm + 1e-7f);
    float* q = g_u + (size_t)b * 9216 + co * 36 + oy * 6;
#pragma unroll
    for (int j = 0; j < 6; j++) q[j] = v[j] * sc;
}

// ---------------- u_hat (fp16 out): block = input capsule i ----------------
__global__ __launch_bounds__(320) void uhat_kernel2(const float* __restrict__ Wc) {
    __shared__ float u_s[2048];
    int i = blockIdx.x;
    int t = threadIdx.x;
    int b2 = t / 40;
    int od4 = t - b2 * 40;

    for (int idx = t; idx < 2048; idx += 320) {
        int b = idx >> 3, e = idx & 7;
        u_s[idx] = g_u[(size_t)b * 9216 + i * 8 + e];
    }
    int od0 = od4 * 4;
    int o = od0 >> 4;
    int d0 = od0 & 15;
    const float* wp = Wc + ((size_t)(o * 1152 + i) * 16 + d0) * 8;
    float w[4][8];
#pragma unroll
    for (int q = 0; q < 4; q++) {
        float4 w0 = *(const float4*)(wp + q * 8);
        float4 w1 = *(const float4*)(wp + q * 8 + 4);
        w[q][0] = w0.x; w[q][1] = w0.y; w[q][2] = w0.z; w[q][3] = w0.w;
        w[q][4] = w1.x; w[q][5] = w1.y; w[q][6] = w1.z; w[q][7] = w1.w;
    }
    __syncthreads();
    for (int bo = 0; bo < 32; bo++) {
        int b = bo * 8 + b2;
        float ue[8];
#pragma unroll
        for (int e = 0; e < 8; e++) ue[e] = u_s[b * 8 + e];
        float acc[4];
#pragma unroll
        for (int q = 0; q < 4; q++) {
            float a = 0.f;
#pragma unroll
            for (int e = 0; e < 8; e++) a += w[q][e] * ue[e];
            acc[q] = a;
        }
        __half2 h0 = __floats2half2_rn(acc[0], acc[1]);
        __half2 h1 = __floats2half2_rn(acc[2], acc[3]);
        __half2* dst = (__half2*)(g_uhat + ((size_t)b * 1152 + i) * 160 + od0);
        dst[0] = h0; dst[1] = h1;
    }
}

// ---------------- dynamic routing (3 iters fused), fp16 u_hat ----------------
__device__ __forceinline__ void route_accum(
    const float uh[5], const float* v0s, const float* v1s,
    int p, int lane, float sacc[5]) {
    float c[5];
    float lg[5];
#pragma unroll
    for (int og = 0; og < 5; og++) {
        float tsum = uh[og] * v0s[og * 32 + lane];
        if (p == 2) tsum += uh[og] * v1s[og * 32 + lane];
        tsum += __shfl_xor_sync(0xffffffffu, tsum, 8);
        tsum += __shfl_xor_sync(0xffffffffu, tsum, 4);
        tsum += __shfl_xor_sync(0xffffffffu, tsum, 2);
        tsum += __shfl_xor_sync(0xffffffffu, tsum, 1);
        lg[og] = tsum;
    }
    float m = lg[0];
#pragma unroll
    for (int og = 1; og < 5; og++) m = fmaxf(m, lg[og]);
    m = fmaxf(m, __shfl_xor_sync(0xffffffffu, m, 16));
    float ssum = 0.f;
#pragma unroll
    for (int og = 0; og < 5; og++) { c[og] = expf(lg[og] - m); ssum += c[og]; }
    ssum += __shfl_xor_sync(0xffffffffu, ssum, 16);
    float inv = 1.f / ssum;
#pragma unroll
    for (int og = 0; og < 5; og++) sacc[og] += (c[og] * inv) * uh[og];
}

__global__ __launch_bounds__(256) void routing_kernel(float* __restrict__ out_len) {
    int b = blockIdx.x;
    int tid = threadIdx.x;
    int lane = tid & 31, warp = tid >> 5;

    __shared__ float v0s[160], v1s[160], v2s[160];
    __shared__ float spart[8 * 160];
    __shared__ float sred[160];
    __shared__ float scale_s[10], len_s[10];
    __shared__ int amax_s;

    const __half* base = g_uhat + (size_t)b * 184320;

    for (int p = 0; p < 3; p++) {
        float sacc[5] = {0.f, 0.f, 0.f, 0.f, 0.f};
        for (int ii = warp; ii < 1152; ii += 16) {
            const __half* pA = base + ii * 160;
            const __half* pB = base + (ii + 8) * 160;
            float uhA[5], uhB[5];
#pragma unroll
            for (int og = 0; og < 5; og++) uhA[og] = __half2float(pA[og * 32 + lane]);
#pragma unroll
            for (int og = 0; og < 5; og++) uhB[og] = __half2float(pB[og * 32 + lane]);
            if (p == 0) {
#pragma unroll
                for (int og = 0; og < 5; og++) sacc[og] += 0.1f * (uhA[og] + uhB[og]);
            } else {
                route_accum(uhA, v0s, v1s, p, lane, sacc);
                route_accum(uhB, v0s, v1s, p, lane, sacc);
            }
        }
#pragma unroll
        for (int og = 0; og < 5; og++) spart[warp * 160 + og * 32 + lane] = sacc[og];
        __syncthreads();
        if (tid < 160) {
            float tot = 0.f;
#pragma unroll
            for (int w = 0; w < 8; w++) tot += spart[w * 160 + tid];
            sred[tid] = tot;
        }
        __syncthreads();
        if (tid < 10) {
            float n2 = 0.f;
#pragma unroll
            for (int d = 0; d < 16; d++) { float xv = sred[tid * 16 + d]; n2 += xv * xv; }
            float nrm = sqrtf(n2);
            scale_s[tid] = (n2 / (1.f + n2)) / (nrm + 1e-7f);
            if (p == 2) len_s[tid] = (n2 / (1.f + n2)) * (nrm / (nrm + 1e-7f));
        }
        __syncthreads();
        float* vdst = (p == 0) ? v0s : ((p == 1) ? v1s : v2s);
        if (tid < 160) vdst[tid] = sred[tid] * scale_s[tid >> 4];
        __syncthreads();
    }

    if (tid == 0) {
        int bi = 0;
        float best = len_s[0];
#pragma unroll
        for (int o = 1; o < 10; o++)
            if (len_s[o] > best) { best = len_s[o]; bi = o; }
        amax_s = bi;
    }
    if (tid < 10) out_len[b * 10 + tid] = len_s[tid];
    __syncthreads();
    if (tid < 160) g_masked[b * 160 + tid] = ((tid >> 4) == amax_s) ? v2s[tid] : 0.f;
}

// ---------------- decoder GEMM (64x64x16 tile, 4x4 micro), epilogue fused ----------------
template <int EPI>
__global__ __launch_bounds__(256) void gemm_epi(
    const float* __restrict__ A, const float* __restrict__ W,
    const float* __restrict__ bias, float* __restrict__ C,
    int M, int N, int K) {
    __shared__ float As[16][64];
    __shared__ float Bs[16][64];
    int t = threadIdx.x;
    int bx = blockIdx.x, by = blockIdx.y;
    int arow = t >> 2, ak = (t & 3) * 4;
    int bkr = t >> 4, bnc = (t & 15) * 4;
    int tx = t & 15, ty = t >> 4;

    float acc[4][4];
#pragma unroll
    for (int i = 0; i < 4; i++)
#pragma unroll
        for (int j = 0; j < 4; j++) acc[i][j] = 0.f;

    for (int kk = 0; kk < K; kk += 16) {
        float4 av = *(const float4*)(A + (size_t)(by * 64 + arow) * K + kk + ak);
        int n0 = bx * 64 + bnc;
        float4 bv = make_float4(0.f, 0.f, 0.f, 0.f);
        if (n0 < N) bv = *(const float4*)(W + (size_t)(kk + bkr) * N + n0);
        As[ak + 0][arow] = av.x; As[ak + 1][arow] = av.y;
        As[ak + 2][arow] = av.z; As[ak + 3][arow] = av.w;
        *(float4*)&Bs[bkr][bnc] = bv;
        __syncthreads();
#pragma unroll
        for (int kr = 0; kr < 16; kr++) {
            float af[4], bf[4];
            *(float4*)af = *(const float4*)&As[kr][ty * 4];
            *(float4*)bf = *(const float4*)&Bs[kr][tx * 4];
#pragma unroll
            for (int mi = 0; mi < 4; mi++)
#pragma unroll
                for (int ni = 0; ni < 4; ni++) acc[mi][ni] += af[mi] * bf[ni];
        }
        __syncthreads();
    }

#pragma unroll
    for (int mi = 0; mi < 4; mi++) {
        int m = by * 64 + ty * 4 + mi;
#pragma unroll
        for (int ni = 0; ni < 4; ni++) {
            int n = bx * 64 + tx * 4 + ni;
            if (n < N) {
                float v = acc[mi][ni] + bias[n];
                if (EPI == 1) v = fmaxf(v, 0.f);
                if (EPI == 2) v = 1.f / (1.f + expf(-v));
                C[(size_t)m * N + n] = v;
            }
        }
    }
}

// ---------------- launch ----------------
extern "C" void kernel_launch(void* const* d_in, const int* in_sizes, int n_in,
                              void* d_out, int out_size) {
    const float* x     = (const float*)d_in[0];
    const float* c1w   = (const float*)d_in[1];
    const float* c1b   = (const float*)d_in[2];
    const float* c2w   = (const float*)d_in[3];
    const float* c2b   = (const float*)d_in[4];
    const float* Wcaps = (const float*)d_in[5];
    const float* dw1   = (const float*)d_in[6];
    const float* db1   = (const float*)d_in[7];
    const float* dw2   = (const float*)d_in[8];
    const float* db2   = (const float*)d_in[9];
    const float* dw3   = (const float*)d_in[10];
    const float* db3   = (const float*)d_in[11];
    float* out = (float*)d_out;

    float* g_d1_ptr; cudaGetSymbolAddress((void**)&g_d1_ptr, g_d1);
    float* g_d2_ptr; cudaGetSymbolAddress((void**)&g_d2_ptr, g_d2);
    float* g_m_ptr;  cudaGetSymbolAddress((void**)&g_m_ptr, g_masked);

    cudaFuncSetAttribute(wtrans_kernel, cudaFuncAttributeMaxDynamicSharedMemorySize,
                         20736 * 4);
    cudaFuncSetAttribute(conv2_mma, cudaFuncAttributeMaxDynamicSharedMemorySize, SM_DYN);

    wtrans_kernel<<<256, 256, 20736 * 4>>>(c2w);
    conv1_kernel<<<dim3(256, 2), 128>>>(x, c1w, c1b);
    conv2_mma<<<dim3(72, 2), 256, SM_DYN>>>(c2b);
    squash_conv_kernel<<<1536, 256>>>();
    uhat_kernel2<<<1152, 320>>>(Wcaps);
    routing_kernel<<<256, 256>>>(out);
    gemm_epi<1><<<dim3(8, 4), 256>>>(g_m_ptr, dw1, db1, g_d1_ptr, 256, 512, 160);
    gemm_epi<1><<<dim3(16, 4), 256>>>(g_d1_ptr, dw2, db2, g_d2_ptr, 256, 1024, 512);
    gemm_epi<2><<<dim3(13, 4), 256>>>(g_d2_ptr, dw3, db3, out + 2560, 256, 784, 1024);
}